// round 3
// baseline (speedup 1.0000x reference)
#include <cuda_runtime.h>
#include <math.h>

// ---------------------------------------------------------------------------
// GraphNet: edge MLP (208->128->64) + mean-agg + node MLP (144->128->64)
//           + global MLP (144->128->16)
// fp32 SIMT baseline, fused gather/scatter.
// edge_index is read as int32 (harness narrows int64 -> int32).
// ---------------------------------------------------------------------------

#define FN   64
#define FG   16
#define HD   128
#define K1   208   // FG + 2*FN + FE
#define KN   144   // FG + FN + FEO
#define TILE 64
#define NT   256

#define S_IN1 212  // padded stride for edge input tile (multiple of 4)
#define S_IN2 148  // padded stride for node input tile
#define S_H   132  // padded stride for hidden tile

#define NMAX 100000

__device__ __align__(16) float g_segsum[(size_t)NMAX * 64];
__device__ __align__(16) float g_cnt[NMAX];
__device__ __align__(16) float g_esum[64];
__device__ __align__(16) float g_nsum[64];

// --------------------------------------------------------------------------
__global__ void zero_kernel(int N) {
    size_t i = (size_t)blockIdx.x * blockDim.x + threadIdx.x;
    size_t t4 = (size_t)N * 16;  // N*64 floats as float4
    if (i < t4) ((float4*)g_segsum)[i] = make_float4(0.f, 0.f, 0.f, 0.f);
    if (i < (size_t)N) g_cnt[i] = 0.f;
    if (i < 64) { g_esum[i] = 0.f; g_nsum[i] = 0.f; }
}

// --------------------------------------------------------------------------
// Edge kernel: per 64-edge tile
//   sIn[64][208] = [g | x[row] | x[col] | ea]
//   h = relu(sIn @ W1 + b1)   (64x128)
//   out = h @ W2 + b2         (64x64)
//   scatter: edge_out, atomic seg_sum[row], cnt[row], block-reduced e_sum
// --------------------------------------------------------------------------
extern __shared__ float smem[];

__global__ __launch_bounds__(NT, 2)
void edge_kernel(const float* __restrict__ x, const int* __restrict__ ei,
                 const float* __restrict__ ea, const float* __restrict__ g,
                 const float* __restrict__ W1, const float* __restrict__ b1,
                 const float* __restrict__ W2, const float* __restrict__ b2,
                 float* __restrict__ eout, int E, int N)
{
    float* sH  = smem;                    // 64 * 132
    float* sIn = smem + TILE * S_H;       // 64 * 212
    float* sW1 = sIn + TILE * S_IN1;      // 16 * 128
    float* sW2 = sIn;                     // 128 * 64 (aliased after GEMM1)

    __shared__ int   sRow[TILE];
    __shared__ int   sCol[TILE];
    __shared__ float part[16][64];

    const int tid = threadIdx.x;
    const int e0  = blockIdx.x * TILE;

    if (tid < TILE) {
        int e = e0 + tid;
        int r = 0, c = 0;
        if (e < E) { r = ei[e]; c = ei[E + e]; }
        // defensive clamp: if index dtype assumption is wrong we want a
        // finite rel_err, not an IMA
        r = min(max(r, 0), N - 1);
        c = min(max(c, 0), N - 1);
        sRow[tid] = r;
        sCol[tid] = c;
    }
    __syncthreads();

    // ---- gather: 52 float4 per edge ----
    for (int i = tid; i < TILE * 52; i += NT) {
        int e = i / 52, c = i % 52;
        int ge = e0 + e;
        float4 v = make_float4(0.f, 0.f, 0.f, 0.f);
        if (ge < E) {
            if (c < 4)       v = ((const float4*)g)[c];
            else if (c < 20) v = ((const float4*)(x + (size_t)sRow[e] * FN))[c - 4];
            else if (c < 36) v = ((const float4*)(x + (size_t)sCol[e] * FN))[c - 20];
            else             v = ((const float4*)(ea + (size_t)ge * FN))[c - 36];
        }
        *((float4*)&sIn[e * S_IN1 + c * 4]) = v;
    }
    __syncthreads();

    const int ty = tid >> 4, tx = tid & 15;
    const int er = ty * 4;  // first edge row of this thread

    // ---- GEMM1: h[64][128] = sIn @ W1 ----
    float acc[4][8];
#pragma unroll
    for (int i = 0; i < 4; i++)
#pragma unroll
        for (int j = 0; j < 8; j++) acc[i][j] = 0.f;

    for (int kb = 0; kb < K1; kb += 16) {
#pragma unroll
        for (int l = 0; l < 2; l++) {
            int idx = tid + l * NT;       // 0..511, 32 float4 per row
            int r = idx >> 5, c4 = idx & 31;
            ((float4*)sW1)[idx] = ((const float4*)(W1 + (size_t)(kb + r) * HD))[c4];
        }
        __syncthreads();
#pragma unroll
        for (int k = 0; k < 16; k++) {
            float a0 = sIn[(er + 0) * S_IN1 + kb + k];
            float a1 = sIn[(er + 1) * S_IN1 + kb + k];
            float a2 = sIn[(er + 2) * S_IN1 + kb + k];
            float a3 = sIn[(er + 3) * S_IN1 + kb + k];
            float bv[8];
            *(float4*)&bv[0] = *(const float4*)&sW1[k * HD + tx * 8];
            *(float4*)&bv[4] = *(const float4*)&sW1[k * HD + tx * 8 + 4];
#pragma unroll
            for (int j = 0; j < 8; j++) {
                acc[0][j] += a0 * bv[j];
                acc[1][j] += a1 * bv[j];
                acc[2][j] += a2 * bv[j];
                acc[3][j] += a3 * bv[j];
            }
        }
        __syncthreads();
    }

    // bias + relu -> sH
    {
        const int j0 = tx * 8;
        float bb[8];
        *(float4*)&bb[0] = *(const float4*)&b1[j0];
        *(float4*)&bb[4] = *(const float4*)&b1[j0 + 4];
#pragma unroll
        for (int i = 0; i < 4; i++) {
#pragma unroll
            for (int j = 0; j < 8; j++) {
                float v = acc[i][j] + bb[j];
                acc[i][j] = v > 0.f ? v : 0.f;
            }
            *(float4*)&sH[(er + i) * S_H + j0]     =
                make_float4(acc[i][0], acc[i][1], acc[i][2], acc[i][3]);
            *(float4*)&sH[(er + i) * S_H + j0 + 4] =
                make_float4(acc[i][4], acc[i][5], acc[i][6], acc[i][7]);
        }
    }

    // load W2 (aliases sIn region; all sIn reads are behind the last sync)
    for (int i = tid; i < HD * 64 / 4; i += NT)
        ((float4*)sW2)[i] = ((const float4*)W2)[i];
    __syncthreads();

    // ---- GEMM2: out[64][64] = sH @ W2 ----
    float acc2[4][4];
#pragma unroll
    for (int i = 0; i < 4; i++)
#pragma unroll
        for (int j = 0; j < 4; j++) acc2[i][j] = 0.f;

#pragma unroll 4
    for (int k = 0; k < HD; k++) {
        float a0 = sH[(er + 0) * S_H + k];
        float a1 = sH[(er + 1) * S_H + k];
        float a2 = sH[(er + 2) * S_H + k];
        float a3 = sH[(er + 3) * S_H + k];
        float4 b = *(const float4*)&sW2[k * 64 + tx * 4];
        acc2[0][0] += a0 * b.x; acc2[0][1] += a0 * b.y; acc2[0][2] += a0 * b.z; acc2[0][3] += a0 * b.w;
        acc2[1][0] += a1 * b.x; acc2[1][1] += a1 * b.y; acc2[1][2] += a1 * b.z; acc2[1][3] += a1 * b.w;
        acc2[2][0] += a2 * b.x; acc2[2][1] += a2 * b.y; acc2[2][2] += a2 * b.z; acc2[2][3] += a2 * b.w;
        acc2[3][0] += a3 * b.x; acc2[3][1] += a3 * b.y; acc2[3][2] += a3 * b.z; acc2[3][3] += a3 * b.w;
    }

    // ---- epilogue: write, scatter, reduce ----
    float4 b2v = *(const float4*)&b2[tx * 4];
    float es0 = 0.f, es1 = 0.f, es2 = 0.f, es3 = 0.f;
#pragma unroll
    for (int i = 0; i < 4; i++) {
        int e = er + i, ge = e0 + e;
        if (ge < E) {
            float v0 = acc2[i][0] + b2v.x;
            float v1 = acc2[i][1] + b2v.y;
            float v2 = acc2[i][2] + b2v.z;
            float v3 = acc2[i][3] + b2v.w;
            *(float4*)&eout[(size_t)ge * 64 + tx * 4] = make_float4(v0, v1, v2, v3);
            int r = sRow[e];
            float* sp = &g_segsum[(size_t)r * 64 + tx * 4];
            atomicAdd(sp + 0, v0);
            atomicAdd(sp + 1, v1);
            atomicAdd(sp + 2, v2);
            atomicAdd(sp + 3, v3);
            if (tx == 0) atomicAdd(&g_cnt[r], 1.0f);
            es0 += v0; es1 += v1; es2 += v2; es3 += v3;
        }
    }
    part[ty][tx * 4 + 0] = es0;
    part[ty][tx * 4 + 1] = es1;
    part[ty][tx * 4 + 2] = es2;
    part[ty][tx * 4 + 3] = es3;
    __syncthreads();
    if (tid < 64) {
        float s = 0.f;
#pragma unroll
        for (int t = 0; t < 16; t++) s += part[t][tid];
        atomicAdd(&g_esum[tid], s);
    }
}

// --------------------------------------------------------------------------
// Node kernel: per 64-node tile
//   sIn[64][144] = [g | x[n] | seg_sum[n]/max(cnt,1)]
// --------------------------------------------------------------------------
__global__ __launch_bounds__(NT, 2)
void node_kernel(const float* __restrict__ x, const float* __restrict__ g,
                 const float* __restrict__ W1, const float* __restrict__ b1,
                 const float* __restrict__ W2, const float* __restrict__ b2,
                 float* __restrict__ nout, int N)
{
    float* sH  = smem;                    // 64 * 132
    float* sIn = smem + TILE * S_H;       // 64 * 148
    float* sW1 = sIn + TILE * S_IN2;      // 16 * 128
    float* sW2 = sIn;                     // 128 * 64 aliased

    __shared__ float part[16][64];

    const int tid = threadIdx.x;
    const int n0  = blockIdx.x * TILE;

    // ---- gather: 36 float4 per node ----
    for (int i = tid; i < TILE * 36; i += NT) {
        int e = i / 36, c = i % 36;
        int n = n0 + e;
        float4 v = make_float4(0.f, 0.f, 0.f, 0.f);
        if (n < N) {
            if (c < 4)       v = ((const float4*)g)[c];
            else if (c < 20) v = ((const float4*)(x + (size_t)n * FN))[c - 4];
            else {
                float4 s = ((const float4*)(g_segsum + (size_t)n * 64))[c - 20];
                float inv = 1.0f / fmaxf(g_cnt[n], 1.0f);
                v = make_float4(s.x * inv, s.y * inv, s.z * inv, s.w * inv);
            }
        }
        *((float4*)&sIn[e * S_IN2 + c * 4]) = v;
    }
    __syncthreads();

    const int ty = tid >> 4, tx = tid & 15;
    const int er = ty * 4;

    float acc[4][8];
#pragma unroll
    for (int i = 0; i < 4; i++)
#pragma unroll
        for (int j = 0; j < 8; j++) acc[i][j] = 0.f;

    for (int kb = 0; kb < KN; kb += 16) {
#pragma unroll
        for (int l = 0; l < 2; l++) {
            int idx = tid + l * NT;
            int r = idx >> 5, c4 = idx & 31;
            ((float4*)sW1)[idx] = ((const float4*)(W1 + (size_t)(kb + r) * HD))[c4];
        }
        __syncthreads();
#pragma unroll
        for (int k = 0; k < 16; k++) {
            float a0 = sIn[(er + 0) * S_IN2 + kb + k];
            float a1 = sIn[(er + 1) * S_IN2 + kb + k];
            float a2 = sIn[(er + 2) * S_IN2 + kb + k];
            float a3 = sIn[(er + 3) * S_IN2 + kb + k];
            float bv[8];
            *(float4*)&bv[0] = *(const float4*)&sW1[k * HD + tx * 8];
            *(float4*)&bv[4] = *(const float4*)&sW1[k * HD + tx * 8 + 4];
#pragma unroll
            for (int j = 0; j < 8; j++) {
                acc[0][j] += a0 * bv[j];
                acc[1][j] += a1 * bv[j];
                acc[2][j] += a2 * bv[j];
                acc[3][j] += a3 * bv[j];
            }
        }
        __syncthreads();
    }

    {
        const int j0 = tx * 8;
        float bb[8];
        *(float4*)&bb[0] = *(const float4*)&b1[j0];
        *(float4*)&bb[4] = *(const float4*)&b1[j0 + 4];
#pragma unroll
        for (int i = 0; i < 4; i++) {
#pragma unroll
            for (int j = 0; j < 8; j++) {
                float v = acc[i][j] + bb[j];
                acc[i][j] = v > 0.f ? v : 0.f;
            }
            *(float4*)&sH[(er + i) * S_H + j0]     =
                make_float4(acc[i][0], acc[i][1], acc[i][2], acc[i][3]);
            *(float4*)&sH[(er + i) * S_H + j0 + 4] =
                make_float4(acc[i][4], acc[i][5], acc[i][6], acc[i][7]);
        }
    }

    for (int i = tid; i < HD * 64 / 4; i += NT)
        ((float4*)sW2)[i] = ((const float4*)W2)[i];
    __syncthreads();

    float acc2[4][4];
#pragma unroll
    for (int i = 0; i < 4; i++)
#pragma unroll
        for (int j = 0; j < 4; j++) acc2[i][j] = 0.f;

#pragma unroll 4
    for (int k = 0; k < HD; k++) {
        float a0 = sH[(er + 0) * S_H + k];
        float a1 = sH[(er + 1) * S_H + k];
        float a2 = sH[(er + 2) * S_H + k];
        float a3 = sH[(er + 3) * S_H + k];
        float4 b = *(const float4*)&sW2[k * 64 + tx * 4];
        acc2[0][0] += a0 * b.x; acc2[0][1] += a0 * b.y; acc2[0][2] += a0 * b.z; acc2[0][3] += a0 * b.w;
        acc2[1][0] += a1 * b.x; acc2[1][1] += a1 * b.y; acc2[1][2] += a1 * b.z; acc2[1][3] += a1 * b.w;
        acc2[2][0] += a2 * b.x; acc2[2][1] += a2 * b.y; acc2[2][2] += a2 * b.z; acc2[2][3] += a2 * b.w;
        acc2[3][0] += a3 * b.x; acc2[3][1] += a3 * b.y; acc2[3][2] += a3 * b.z; acc2[3][3] += a3 * b.w;
    }

    float4 b2v = *(const float4*)&b2[tx * 4];
    float es0 = 0.f, es1 = 0.f, es2 = 0.f, es3 = 0.f;
#pragma unroll
    for (int i = 0; i < 4; i++) {
        int e = er + i, n = n0 + e;
        if (n < N) {
            float v0 = acc2[i][0] + b2v.x;
            float v1 = acc2[i][1] + b2v.y;
            float v2 = acc2[i][2] + b2v.z;
            float v3 = acc2[i][3] + b2v.w;
            *(float4*)&nout[(size_t)n * 64 + tx * 4] = make_float4(v0, v1, v2, v3);
            es0 += v0; es1 += v1; es2 += v2; es3 += v3;
        }
    }
    part[ty][tx * 4 + 0] = es0;
    part[ty][tx * 4 + 1] = es1;
    part[ty][tx * 4 + 2] = es2;
    part[ty][tx * 4 + 3] = es3;
    __syncthreads();
    if (tid < 64) {
        float s = 0.f;
#pragma unroll
        for (int t = 0; t < 16; t++) s += part[t][tid];
        atomicAdd(&g_nsum[tid], s);
    }
}

// --------------------------------------------------------------------------
__global__ void global_kernel(const float* __restrict__ g,
                              const float* __restrict__ Wg1, const float* __restrict__ bg1,
                              const float* __restrict__ Wg2, const float* __restrict__ bg2,
                              float* __restrict__ out, int N, int E)
{
    __shared__ float in[KN];
    __shared__ float h[HD];
    int t = threadIdx.x;
    if (t < 64)        in[t] = g_nsum[t] / (float)N;
    else if (t < 128)  in[t] = g_esum[t - 64] / (float)E;
    else if (t < 144)  in[t] = g[t - 128];
    __syncthreads();
    if (t < HD) {
        float s = bg1[t];
        for (int k = 0; k < KN; k++) s += in[k] * Wg1[(size_t)k * HD + t];
        h[t] = fmaxf(s, 0.f);
    }
    __syncthreads();
    if (t < FG) {
        float s = bg2[t];
        for (int k = 0; k < HD; k++) s += h[k] * Wg2[(size_t)k * FG + t];
        out[t] = s;
    }
}

// --------------------------------------------------------------------------
extern "C" void kernel_launch(void* const* d_in, const int* in_sizes, int n_in,
                              void* d_out, int out_size)
{
    const float* x   = (const float*)d_in[0];
    const int*   ei  = (const int*)d_in[1];
    const float* ea  = (const float*)d_in[2];
    const float* g   = (const float*)d_in[3];
    const float* We1 = (const float*)d_in[4];
    const float* be1 = (const float*)d_in[5];
    const float* We2 = (const float*)d_in[6];
    const float* be2 = (const float*)d_in[7];
    const float* Wn1 = (const float*)d_in[8];
    const float* bn1 = (const float*)d_in[9];
    const float* Wn2 = (const float*)d_in[10];
    const float* bn2 = (const float*)d_in[11];
    const float* Wg1 = (const float*)d_in[12];
    const float* bg1 = (const float*)d_in[13];
    const float* Wg2 = (const float*)d_in[14];
    const float* bg2 = (const float*)d_in[15];

    int N = in_sizes[0] / FN;
    int E = in_sizes[1] / 2;

    float* eout = (float*)d_out;
    float* nout = eout + (size_t)E * 64;
    float* gout = nout + (size_t)N * 64;

    const int SMEM_EDGE = (TILE * S_H + TILE * S_IN1 + 16 * HD) * (int)sizeof(float);
    const int SMEM_NODE = (TILE * S_H + TILE * S_IN2 + 16 * HD) * (int)sizeof(float);

    cudaFuncSetAttribute(edge_kernel, cudaFuncAttributeMaxDynamicSharedMemorySize, SMEM_EDGE);
    cudaFuncSetAttribute(node_kernel, cudaFuncAttributeMaxDynamicSharedMemorySize, SMEM_NODE);

    int zthreads = 256;
    int zblocks = (N * 16 + zthreads - 1) / zthreads;
    zero_kernel<<<zblocks, zthreads>>>(N);

    edge_kernel<<<(E + TILE - 1) / TILE, NT, SMEM_EDGE>>>(
        x, ei, ea, g, We1, be1, We2, be2, eout, E, N);

    node_kernel<<<(N + TILE - 1) / TILE, NT, SMEM_NODE>>>(
        x, g, Wn1, bn1, Wn2, bn2, nout, N);

    global_kernel<<<1, 160>>>(g, Wg1, bg1, Wg2, bg2, gout, N, E);
}

// round 5
// speedup vs baseline: 1.6009x; 1.6009x over previous
#include <cuda_runtime.h>
#include <cuda_bf16.h>
#include <stdint.h>
#include <math.h>

#define NMAX 100000

__device__ __align__(16) float g_segsum[(size_t)NMAX * 64];
__device__ float g_cnt[NMAX];
__device__ float g_esum[64];
__device__ float g_nsum[64];
// bf16 hi|lo packed, padded strides (W1: 136 cols, W2: 72 cols)
__device__ __align__(16) unsigned char g_w1[113152];
__device__ __align__(16) unsigned char g_w2[36864];
__device__ __align__(16) unsigned char g_wn1[78336];
__device__ __align__(16) unsigned char g_wn2[36864];

// ---------------- helpers ----------------
__device__ __forceinline__ uint32_t smem_u32(const void* p) {
    uint32_t a;
    asm("{ .reg .u64 t; cvta.to.shared.u64 t, %1; cvt.u32.u64 %0, t; }" : "=r"(a) : "l"(p));
    return a;
}
#define LDSM_X4(r, a) asm volatile( \
    "ldmatrix.sync.aligned.m8n8.x4.shared.b16 {%0,%1,%2,%3}, [%4];" \
    : "=r"((r)[0]), "=r"((r)[1]), "=r"((r)[2]), "=r"((r)[3]) : "r"(a))
#define LDSM_X4T(r, a) asm volatile( \
    "ldmatrix.sync.aligned.m8n8.x4.trans.shared.b16 {%0,%1,%2,%3}, [%4];" \
    : "=r"((r)[0]), "=r"((r)[1]), "=r"((r)[2]), "=r"((r)[3]) : "r"(a))
#define MMA16816(d, a, b) asm volatile( \
    "mma.sync.aligned.m16n8k16.row.col.f32.bf16.bf16.f32 " \
    "{%0,%1,%2,%3}, {%4,%5,%6,%7}, {%8,%9}, {%0,%1,%2,%3};" \
    : "+f"((d)[0]), "+f"((d)[1]), "+f"((d)[2]), "+f"((d)[3]) \
    : "r"((a)[0]), "r"((a)[1]), "r"((a)[2]), "r"((a)[3]), "r"((b)[0]), "r"((b)[1]))

__device__ __forceinline__ void split2(float v0, float v1, uint32_t& h, uint32_t& l) {
    asm("cvt.rn.bf16x2.f32 %0, %1, %2;" : "=r"(h) : "f"(v1), "f"(v0));
    float h0 = __uint_as_float(h << 16);
    float h1 = __uint_as_float(h & 0xffff0000u);
    asm("cvt.rn.bf16x2.f32 %0, %1, %2;" : "=r"(l) : "f"(v1 - h1), "f"(v0 - h0));
}
__device__ __forceinline__ void redv4(float* p, float a, float b, float c, float d) {
    asm volatile("{ .reg .u64 q; cvta.to.global.u64 q, %0;\n"
                 "red.global.add.v4.f32 [q], {%1,%2,%3,%4}; }"
                 :: "l"(p), "f"(a), "f"(b), "f"(c), "f"(d) : "memory");
}

// ---------------- setup ----------------
__global__ void zero_kernel(int N) {
    size_t i = (size_t)blockIdx.x * blockDim.x + threadIdx.x;
    if (i < (size_t)N * 16) ((float4*)g_segsum)[i] = make_float4(0.f, 0.f, 0.f, 0.f);
    if (i < (size_t)N) g_cnt[i] = 0.f;
    if (i < 64) { g_esum[i] = 0.f; g_nsum[i] = 0.f; }
}
__device__ __forceinline__ void wsplit(unsigned char* b, int halfoff, int off2, float v) {
    __nv_bfloat16 h = __float2bfloat16(v);
    *(__nv_bfloat16*)(b + off2) = h;
    *(__nv_bfloat16*)(b + halfoff + off2) = __float2bfloat16(v - __bfloat162float(h));
}
__global__ void prep_weights(const float* W1, const float* W2,
                             const float* Wn1, const float* Wn2) {
    int i = blockIdx.x * blockDim.x + threadIdx.x;
    if (i < 26624) { int k = i >> 7, n = i & 127; wsplit(g_w1, 56576, (k * 136 + n) * 2, W1[i]); return; }
    i -= 26624;
    if (i < 8192)  { int k = i >> 6, n = i & 63;  wsplit(g_w2, 18432, (k * 72 + n) * 2, W2[i]); return; }
    i -= 8192;
    if (i < 18432) { int k = i >> 7, n = i & 127; wsplit(g_wn1, 39168, (k * 136 + n) * 2, Wn1[i]); return; }
    i -= 18432;
    if (i < 8192)  { int k = i >> 6, n = i & 63;  wsplit(g_wn2, 18432, (k * 72 + n) * 2, Wn2[i]); }
}

// ---------------- fused 2-layer MLP on one 64-row tile ----------------
// A (bf16 hi/lo) rows 0..63, K=16*KC1, stride SA (odd*8). W1 stride 136, W2 stride 72.
// H (64x128) aliases A region. D2 (64x64 fp32, +bias) written to sD2 stride 68.
template<int SA, int KC1>
__device__ __forceinline__ void tile_mlp(char* dsm, uint32_t sbase,
    uint32_t offAhi, uint32_t offAlo, uint32_t offW1hi, uint32_t offW1lo,
    uint32_t offW2hi, uint32_t offW2lo, uint32_t offD2,
    const float* b1s, const float* b2s, int wid, int lane)
{
    const int wm = wid & 1, wn = wid >> 1;
    const int r0 = 32 * wm, n0 = 32 * wn;

    // ---- GEMM1: 32x32 per warp over K ----
    float d1[2][4][4];
#pragma unroll
    for (int m = 0; m < 2; m++)
#pragma unroll
        for (int nt = 0; nt < 4; nt++)
#pragma unroll
            for (int j = 0; j < 4; j++) d1[m][nt][j] = 0.f;

    const uint32_t aoff = (uint32_t)(((lane & 15) * SA + (lane >> 4) * 8) * 2);
    const uint32_t boff = (uint32_t)(((lane & 15) * 136 + (lane >> 4) * 8) * 2);
    const uint32_t aAh = sbase + offAhi + r0 * SA * 2 + aoff;
    const uint32_t aAl = sbase + offAlo + r0 * SA * 2 + aoff;
    const uint32_t bW1 = sbase + offW1hi + boff + n0 * 2;
    const uint32_t dW1 = offW1lo - offW1hi;

    for (int kc = 0; kc < KC1; kc++) {
        const uint32_t kb = kc * 32;  // kk*2 bytes
        uint32_t ah0[4], ah1[4], al0[4], al1[4];
        LDSM_X4(ah0, aAh + kb);
        LDSM_X4(ah1, aAh + 16 * SA * 2 + kb);
        LDSM_X4(al0, aAl + kb);
        LDSM_X4(al1, aAl + 16 * SA * 2 + kb);
        uint32_t bh[2][4], bl[2][4];
#pragma unroll
        for (int g2 = 0; g2 < 2; g2++) {
            uint32_t ba = bW1 + kc * 16 * 272 + g2 * 32;
            LDSM_X4T(bh[g2], ba);
            LDSM_X4T(bl[g2], ba + dW1);
        }
#pragma unroll
        for (int nt = 0; nt < 4; nt++) {
            uint32_t* bhp = &bh[nt >> 1][(nt & 1) * 2];
            uint32_t* blp = &bl[nt >> 1][(nt & 1) * 2];
            MMA16816(d1[0][nt], ah0, bhp);
            MMA16816(d1[0][nt], ah0, blp);
            MMA16816(d1[0][nt], al0, bhp);
            MMA16816(d1[1][nt], ah1, bhp);
            MMA16816(d1[1][nt], ah1, blp);
            MMA16816(d1[1][nt], al1, bhp);
        }
    }

    __syncthreads();   // all GEMM1 reads of A done before H overwrites it

    // ---- epi1: H = relu(D1 + b1) -> bf16 hi/lo (stride 136), aliases A ----
#pragma unroll
    for (int m = 0; m < 2; m++)
#pragma unroll
        for (int nt = 0; nt < 4; nt++) {
            int c = n0 + 8 * nt + (lane & 3) * 2;
            int R = r0 + 16 * m + (lane >> 2);
            uint32_t h, l;
            float v0 = fmaxf(d1[m][nt][0] + b1s[c], 0.f);
            float v1 = fmaxf(d1[m][nt][1] + b1s[c + 1], 0.f);
            split2(v0, v1, h, l);
            *(uint32_t*)(dsm + offAhi + (R * 136 + c) * 2) = h;
            *(uint32_t*)(dsm + offAlo + (R * 136 + c) * 2) = l;
            float v2 = fmaxf(d1[m][nt][2] + b1s[c], 0.f);
            float v3 = fmaxf(d1[m][nt][3] + b1s[c + 1], 0.f);
            split2(v2, v3, h, l);
            *(uint32_t*)(dsm + offAhi + ((R + 8) * 136 + c) * 2) = h;
            *(uint32_t*)(dsm + offAlo + ((R + 8) * 136 + c) * 2) = l;
        }

    __syncthreads();   // H complete

    // ---- GEMM2: 32x16 per warp, K=128 ----
    float d2[2][2][4];
#pragma unroll
    for (int m = 0; m < 2; m++)
#pragma unroll
        for (int nt = 0; nt < 2; nt++)
#pragma unroll
            for (int j = 0; j < 4; j++) d2[m][nt][j] = 0.f;

    const uint32_t hoff = (uint32_t)(((lane & 15) * 136 + (lane >> 4) * 8) * 2);
    const uint32_t w2off = (uint32_t)(((lane & 15) * 72 + (lane >> 4) * 8) * 2);
    const uint32_t aH = sbase + offAhi + r0 * 272 + hoff;
    const uint32_t dH = offAlo - offAhi;
    const uint32_t bW2 = sbase + offW2hi + w2off + (16 * wn) * 2;
    const uint32_t dW2 = offW2lo - offW2hi;

#pragma unroll
    for (int kc = 0; kc < 8; kc++) {
        const uint32_t kb = kc * 32;
        uint32_t ah0[4], ah1[4], al0[4], al1[4];
        LDSM_X4(ah0, aH + kb);
        LDSM_X4(ah1, aH + 16 * 272 + kb);
        LDSM_X4(al0, aH + dH + kb);
        LDSM_X4(al1, aH + dH + 16 * 272 + kb);
        uint32_t bh[4], bl[4];
        uint32_t ba = bW2 + kc * 16 * 144;
        LDSM_X4T(bh, ba);
        LDSM_X4T(bl, ba + dW2);
#pragma unroll
        for (int nt = 0; nt < 2; nt++) {
            MMA16816(d2[0][nt], ah0, &bh[2 * nt]);
            MMA16816(d2[0][nt], ah0, &bl[2 * nt]);
            MMA16816(d2[0][nt], al0, &bh[2 * nt]);
            MMA16816(d2[1][nt], ah1, &bh[2 * nt]);
            MMA16816(d2[1][nt], ah1, &bl[2 * nt]);
            MMA16816(d2[1][nt], al1, &bh[2 * nt]);
        }
    }

    // ---- epi2: D2 + b2 -> sD2 fp32 (stride 68) ----
    float* sD2 = (float*)(dsm + offD2);
#pragma unroll
    for (int m = 0; m < 2; m++)
#pragma unroll
        for (int nt = 0; nt < 2; nt++) {
            int c = 16 * wn + 8 * nt + (lane & 3) * 2;
            int R = r0 + 16 * m + (lane >> 2);
            *(float2*)&sD2[R * 68 + c] =
                make_float2(d2[m][nt][0] + b2s[c], d2[m][nt][1] + b2s[c + 1]);
            *(float2*)&sD2[(R + 8) * 68 + c] =
                make_float2(d2[m][nt][2] + b2s[c], d2[m][nt][3] + b2s[c + 1]);
        }
}

// ---------------- edge kernel ----------------
extern __shared__ char dsm[];

#define E_W1HI 0u
#define E_W1LO 56576u
#define E_W2HI 113152u
#define E_W2LO 131584u
#define E_AHI  150016u
#define E_ALO  177664u
#define E_D2F  205312u
#define E_SMEM 222720

__global__ __launch_bounds__(256, 1)
void edge_tc(const float* __restrict__ x, const int* __restrict__ ei,
             const float* __restrict__ ea, const float* __restrict__ gf,
             const float* __restrict__ b1, const float* __restrict__ b2,
             float* __restrict__ eout, int E, int N, int ntiles)
{
    __shared__ float b1s[128], b2s[64], redbuf[64];
    const int tid = threadIdx.x, wid = tid >> 5, lane = tid & 31;
    const uint32_t sbase = smem_u32(dsm);

    { // stage weights (already split + padded)
        const uint4* s1 = (const uint4*)g_w1; uint4* d1 = (uint4*)dsm;
        for (int i = tid; i < 7072; i += 256) d1[i] = s1[i];
        const uint4* s2 = (const uint4*)g_w2; uint4* d2 = (uint4*)(dsm + E_W2HI);
        for (int i = tid; i < 2304; i += 256) d2[i] = s2[i];
    }
    if (tid < 128) b1s[tid] = b1[tid];
    if (tid < 64)  { b2s[tid] = b2[tid]; redbuf[tid] = 0.f; }

    float acc[4] = {0.f, 0.f, 0.f, 0.f};

    for (int t = blockIdx.x; t < ntiles; t += gridDim.x) {
        // ---- gather: 52 float4 per edge -> A hi/lo ----
        for (int i = tid; i < 64 * 52; i += 256) {
            int e = i / 52, c4 = i % 52;
            int ge = t * 64 + e;
            float4 v = make_float4(0.f, 0.f, 0.f, 0.f);
            if (ge < E) {
                if (c4 < 4) v = ((const float4*)gf)[c4];
                else if (c4 < 20) {
                    int r = ei[ge]; r = min(max(r, 0), N - 1);
                    v = ((const float4*)(x + (size_t)r * 64))[c4 - 4];
                } else if (c4 < 36) {
                    int c = ei[E + ge]; c = min(max(c, 0), N - 1);
                    v = ((const float4*)(x + (size_t)c * 64))[c4 - 20];
                } else
                    v = ((const float4*)(ea + (size_t)ge * 64))[c4 - 36];
            }
            uint32_t h0, l0, h1, l1;
            split2(v.x, v.y, h0, l0);
            split2(v.z, v.w, h1, l1);
            uint32_t off = (uint32_t)((e * 216 + c4 * 4) * 2);
            *(uint32_t*)(dsm + E_AHI + off) = h0;
            *(uint32_t*)(dsm + E_AHI + off + 4) = h1;
            *(uint32_t*)(dsm + E_ALO + off) = l0;
            *(uint32_t*)(dsm + E_ALO + off + 4) = l1;
        }
        __syncthreads();

        tile_mlp<216, 13>(dsm, sbase, E_AHI, E_ALO, E_W1HI, E_W1LO,
                          E_W2HI, E_W2LO, E_D2F, b1s, b2s, wid, lane);
        __syncthreads();

        // ---- scatter ----
        const float* sD2 = (const float*)(dsm + E_D2F);
#pragma unroll
        for (int i = 0; i < 4; i++) {
            int row = i * 16 + (tid >> 4);
            int ge = t * 64 + row;
            if (ge < E) {
                int r = ei[ge]; r = min(max(r, 0), N - 1);
                int c4 = (tid & 15) * 4;
                float4 v = *(const float4*)&sD2[row * 68 + c4];
                *(float4*)(eout + (size_t)ge * 64 + c4) = v;
                redv4(g_segsum + (size_t)r * 64 + c4, v.x, v.y, v.z, v.w);
                if ((tid & 15) == 0) atomicAdd(&g_cnt[r], 1.f);
                acc[0] += v.x; acc[1] += v.y; acc[2] += v.z; acc[3] += v.w;
            }
        }
        __syncthreads();
    }
#pragma unroll
    for (int j = 0; j < 4; j++) atomicAdd(&redbuf[(tid & 15) * 4 + j], acc[j]);
    __syncthreads();
    if (tid < 64) atomicAdd(&g_esum[tid], redbuf[tid]);
}

// ---------------- node kernel ----------------
#define N_W1HI 0u
#define N_W1LO 39168u
#define N_W2HI 78336u
#define N_W2LO 96768u
#define N_AHI  115200u
#define N_ALO  134656u
#define N_D2F  154112u
#define N_SMEM 171520

__global__ __launch_bounds__(256, 1)
void node_tc(const float* __restrict__ x, const float* __restrict__ gf,
             const float* __restrict__ b1, const float* __restrict__ b2,
             float* __restrict__ nout, int N, int ntiles)
{
    __shared__ float b1s[128], b2s[64], redbuf[64];
    const int tid = threadIdx.x, wid = tid >> 5, lane = tid & 31;
    const uint32_t sbase = smem_u32(dsm);

    {
        const uint4* s1 = (const uint4*)g_wn1; uint4* d1 = (uint4*)dsm;
        for (int i = tid; i < 4896; i += 256) d1[i] = s1[i];
        const uint4* s2 = (const uint4*)g_wn2; uint4* d2 = (uint4*)(dsm + N_W2HI);
        for (int i = tid; i < 2304; i += 256) d2[i] = s2[i];
    }
    if (tid < 128) b1s[tid] = b1[tid];
    if (tid < 64)  { b2s[tid] = b2[tid]; redbuf[tid] = 0.f; }

    float acc[4] = {0.f, 0.f, 0.f, 0.f};

    for (int t = blockIdx.x; t < ntiles; t += gridDim.x) {
        for (int i = tid; i < 64 * 36; i += 256) {
            int e = i / 36, c4 = i % 36;
            int n = t * 64 + e;
            float4 v = make_float4(0.f, 0.f, 0.f, 0.f);
            if (n < N) {
                if (c4 < 4) v = ((const float4*)gf)[c4];
                else if (c4 < 20)
                    v = ((const float4*)(x + (size_t)n * 64))[c4 - 4];
                else {
                    float4 s = ((const float4*)(g_segsum + (size_t)n * 64))[c4 - 20];
                    float inv = 1.0f / fmaxf(g_cnt[n], 1.0f);
                    v = make_float4(s.x * inv, s.y * inv, s.z * inv, s.w * inv);
                }
            }
            uint32_t h0, l0, h1, l1;
            split2(v.x, v.y, h0, l0);
            split2(v.z, v.w, h1, l1);
            uint32_t off = (uint32_t)((e * 152 + c4 * 4) * 2);
            *(uint32_t*)(dsm + N_AHI + off) = h0;
            *(uint32_t*)(dsm + N_AHI + off + 4) = h1;
            *(uint32_t*)(dsm + N_ALO + off) = l0;
            *(uint32_t*)(dsm + N_ALO + off + 4) = l1;
        }
        __syncthreads();

        tile_mlp<152, 9>(dsm, sbase, N_AHI, N_ALO, N_W1HI, N_W1LO,
                         N_W2HI, N_W2LO, N_D2F, b1s, b2s, wid, lane);
        __syncthreads();

        const float* sD2 = (const float*)(dsm + N_D2F);
#pragma unroll
        for (int i = 0; i < 4; i++) {
            int row = i * 16 + (tid >> 4);
            int n = t * 64 + row;
            if (n < N) {
                int c4 = (tid & 15) * 4;
                float4 v = *(const float4*)&sD2[row * 68 + c4];
                *(float4*)(nout + (size_t)n * 64 + c4) = v;
                acc[0] += v.x; acc[1] += v.y; acc[2] += v.z; acc[3] += v.w;
            }
        }
        __syncthreads();
    }
#pragma unroll
    for (int j = 0; j < 4; j++) atomicAdd(&redbuf[(tid & 15) * 4 + j], acc[j]);
    __syncthreads();
    if (tid < 64) atomicAdd(&g_nsum[tid], redbuf[tid]);
}

// ---------------- global kernel ----------------
__global__ void global_kernel(const float* __restrict__ g,
                              const float* __restrict__ Wg1, const float* __restrict__ bg1,
                              const float* __restrict__ Wg2, const float* __restrict__ bg2,
                              float* __restrict__ out, int N, int E)
{
    __shared__ float in[144], h[128];
    int t = threadIdx.x;
    if (t < 64)       in[t] = g_nsum[t] / (float)N;
    else if (t < 128) in[t] = g_esum[t - 64] / (float)E;
    else if (t < 144) in[t] = g[t - 128];
    __syncthreads();
    if (t < 128) {
        float s = bg1[t];
        for (int k = 0; k < 144; k++) s += in[k] * Wg1[(size_t)k * 128 + t];
        h[t] = fmaxf(s, 0.f);
    }
    __syncthreads();
    if (t < 16) {
        float s = bg2[t];
        for (int k = 0; k < 128; k++) s += h[k] * Wg2[(size_t)k * 16 + t];
        out[t] = s;
    }
}

// ---------------- launch ----------------
extern "C" void kernel_launch(void* const* d_in, const int* in_sizes, int n_in,
                              void* d_out, int out_size)
{
    const float* x   = (const float*)d_in[0];
    const int*   ei  = (const int*)d_in[1];
    const float* ea  = (const float*)d_in[2];
    const float* g   = (const float*)d_in[3];
    const float* We1 = (const float*)d_in[4];
    const float* be1 = (const float*)d_in[5];
    const float* We2 = (const float*)d_in[6];
    const float* be2 = (const float*)d_in[7];
    const float* Wn1 = (const float*)d_in[8];
    const float* bn1 = (const float*)d_in[9];
    const float* Wn2 = (const float*)d_in[10];
    const float* bn2 = (const float*)d_in[11];
    const float* Wg1 = (const float*)d_in[12];
    const float* bg1 = (const float*)d_in[13];
    const float* Wg2 = (const float*)d_in[14];
    const float* bg2 = (const float*)d_in[15];

    int N = in_sizes[0] / 64;
    int E = in_sizes[1] / 2;
    float* eout = (float*)d_out;
    float* nout = eout + (size_t)E * 64;
    float* gout = nout + (size_t)N * 64;

    cudaFuncSetAttribute(edge_tc, cudaFuncAttributeMaxDynamicSharedMemorySize, E_SMEM);
    cudaFuncSetAttribute(node_tc, cudaFuncAttributeMaxDynamicSharedMemorySize, N_SMEM);

    zero_kernel<<<(N * 16 + 255) / 256, 256>>>(N);
    prep_weights<<<(61440 + 255) / 256, 256>>>(We1, We2, Wn1, Wn2);

    int etiles = (E + 63) / 64;
    int ntl    = (N + 63) / 64;
    edge_tc<<<148, 256, E_SMEM>>>(x, ei, ea, g, be1, be2, eout, E, N, etiles);
    node_tc<<<148, 256, N_SMEM>>>(x, g, bn1, bn2, nout, N, ntl);
    global_kernel<<<1, 160>>>(g, Wg1, bg1, Wg2, bg2, gout, N, E);
}

// round 6
// speedup vs baseline: 2.8022x; 1.7504x over previous
#include <cuda_runtime.h>
#include <cuda_bf16.h>
#include <stdint.h>
#include <math.h>

#define NMAX 100000

__device__ __align__(16) float g_segsum[(size_t)NMAX * 64];
__device__ float g_cnt[NMAX];
__device__ float g_esum[64];
__device__ float g_nsum[64];

// weights in MMA-fragment order: uint4 = {hi.b0, hi.b1, lo.b0, lo.b1}
// index [kc][nt8][lane]
__device__ __align__(16) uint4 g_w1f[13 * 16 * 32];   // edge W1: K=208, N=128
__device__ __align__(16) uint4 g_w2f[8 * 8 * 32];     // edge W2: K=128, N=64
__device__ __align__(16) uint4 g_wn1f[9 * 16 * 32];   // node W1: K=144, N=128
__device__ __align__(16) uint4 g_wn2f[8 * 8 * 32];    // node W2: K=128, N=64

// ---------------- helpers ----------------
__device__ __forceinline__ uint32_t smem_u32(const void* p) {
    uint32_t a;
    asm("{ .reg .u64 t; cvta.to.shared.u64 t, %1; cvt.u32.u64 %0, t; }" : "=r"(a) : "l"(p));
    return a;
}
#define LDSM_X4(r, a) asm volatile( \
    "ldmatrix.sync.aligned.m8n8.x4.shared.b16 {%0,%1,%2,%3}, [%4];" \
    : "=r"((r)[0]), "=r"((r)[1]), "=r"((r)[2]), "=r"((r)[3]) : "r"(a))
#define MMA16816(d, a, b0, b1) asm volatile( \
    "mma.sync.aligned.m16n8k16.row.col.f32.bf16.bf16.f32 " \
    "{%0,%1,%2,%3}, {%4,%5,%6,%7}, {%8,%9}, {%0,%1,%2,%3};" \
    : "+f"((d)[0]), "+f"((d)[1]), "+f"((d)[2]), "+f"((d)[3]) \
    : "r"((a)[0]), "r"((a)[1]), "r"((a)[2]), "r"((a)[3]), "r"(b0), "r"(b1))

__device__ __forceinline__ void split2(float v0, float v1, uint32_t& h, uint32_t& l) {
    asm("cvt.rn.bf16x2.f32 %0, %1, %2;" : "=r"(h) : "f"(v1), "f"(v0));
    float h0 = __uint_as_float(h << 16);
    float h1 = __uint_as_float(h & 0xffff0000u);
    asm("cvt.rn.bf16x2.f32 %0, %1, %2;" : "=r"(l) : "f"(v1 - h1), "f"(v0 - h0));
}
__device__ __forceinline__ void redv4(float* p, float a, float b, float c, float d) {
    asm volatile("{ .reg .u64 q; cvta.to.global.u64 q, %0;\n"
                 "red.global.add.v4.f32 [q], {%1,%2,%3,%4}; }"
                 :: "l"(p), "f"(a), "f"(b), "f"(c), "f"(d) : "memory");
}

// ---------------- setup ----------------
__global__ void zero_kernel(int N) {
    size_t i = (size_t)blockIdx.x * blockDim.x + threadIdx.x;
    if (i < (size_t)N * 16) ((float4*)g_segsum)[i] = make_float4(0.f, 0.f, 0.f, 0.f);
    if (i < (size_t)N) g_cnt[i] = 0.f;
    if (i < 64) { g_esum[i] = 0.f; g_nsum[i] = 0.f; }
}

// build one fragment uint4 from source W[k][n] (row-major, stride ncols)
__device__ __forceinline__ uint4 mkfrag(const float* W, int ncols, int kc, int nt8, int lane) {
    int k0 = kc * 16 + 2 * (lane & 3);
    int n  = nt8 * 8 + (lane >> 2);
    float w00 = W[(size_t)k0 * ncols + n];
    float w01 = W[(size_t)(k0 + 1) * ncols + n];
    float w10 = W[(size_t)(k0 + 8) * ncols + n];
    float w11 = W[(size_t)(k0 + 9) * ncols + n];
    uint32_t h0, l0, h1, l1;
    split2(w00, w01, h0, l0);
    split2(w10, w11, h1, l1);
    return make_uint4(h0, h1, l0, l1);
}

__global__ void prep_weights(const float* We1, const float* We2,
                             const float* Wn1, const float* Wn2) {
    int i = blockIdx.x * blockDim.x + threadIdx.x;
    if (i < 13 * 16 * 32) {
        int kc = i >> 9, r = i & 511;
        g_w1f[i] = mkfrag(We1, 128, kc, r >> 5, r & 31);
        return;
    }
    i -= 13 * 16 * 32;
    if (i < 8 * 8 * 32) {
        int kc = i >> 8, r = i & 255;
        g_w2f[i] = mkfrag(We2, 64, kc, r >> 5, r & 31);
        return;
    }
    i -= 8 * 8 * 32;
    if (i < 9 * 16 * 32) {
        int kc = i >> 9, r = i & 511;
        g_wn1f[i] = mkfrag(Wn1, 128, kc, r >> 5, r & 31);
        return;
    }
    i -= 9 * 16 * 32;
    if (i < 8 * 8 * 32) {
        int kc = i >> 8, r = i & 255;
        g_wn2f[i] = mkfrag(Wn2, 64, kc, r >> 5, r & 31);
    }
}

// ---------------- fused 2-layer MLP on one 64-row tile ----------------
// A bf16 hi/lo in smem (stride SA), H (stride 136) overwrites A, D2 fp32 -> offD2 (stride 68).
// Warp w owns GEMM1 cols [16w,16w+16) and GEMM2 cols [8w,8w+8).
template<int SA, int KC1>
__device__ __forceinline__ void tile_mlp(char* sm, uint32_t sbase,
    uint32_t offAhi, uint32_t offAlo, uint32_t offD2,
    const uint4* __restrict__ W1f, const uint4* __restrict__ W2f,
    const float* b1s, const float* b2s, int wid, int lane)
{
    // ---- GEMM1: 64 x 16 per warp over K = 16*KC1 ----
    float d1[4][2][4];
#pragma unroll
    for (int m = 0; m < 4; m++)
#pragma unroll
        for (int nt = 0; nt < 2; nt++)
#pragma unroll
            for (int j = 0; j < 4; j++) d1[m][nt][j] = 0.f;

    const uint32_t aoff = (uint32_t)(((lane & 15) * SA + (lane >> 4) * 8) * 2);
    const uint32_t aAh = sbase + offAhi + aoff;
    const uint32_t aAl = sbase + offAlo + aoff;
    const uint4* __restrict__ w1p = W1f + (2 * wid) * 32 + lane;

    for (int kc = 0; kc < KC1; kc++) {
        uint32_t ah[4][4], al[4][4];
#pragma unroll
        for (int m = 0; m < 4; m++) {
            LDSM_X4(ah[m], aAh + (uint32_t)(m * 16 * SA * 2) + kc * 32);
            LDSM_X4(al[m], aAl + (uint32_t)(m * 16 * SA * 2) + kc * 32);
        }
        uint4 w0 = __ldg(w1p + kc * 512);
        uint4 w1 = __ldg(w1p + kc * 512 + 32);
#pragma unroll
        for (int m = 0; m < 4; m++) {
            MMA16816(d1[m][0], ah[m], w0.x, w0.y);
            MMA16816(d1[m][0], ah[m], w0.z, w0.w);
            MMA16816(d1[m][0], al[m], w0.x, w0.y);
            MMA16816(d1[m][1], ah[m], w1.x, w1.y);
            MMA16816(d1[m][1], ah[m], w1.z, w1.w);
            MMA16816(d1[m][1], al[m], w1.x, w1.y);
        }
    }
    __syncthreads();   // all GEMM1 reads of A done before H overwrites it

    // ---- epi1: H = relu(D1 + b1) -> bf16 hi/lo (stride 136) aliasing A ----
#pragma unroll
    for (int m = 0; m < 4; m++)
#pragma unroll
        for (int nt = 0; nt < 2; nt++) {
            int c = 16 * wid + 8 * nt + (lane & 3) * 2;
            int R = 16 * m + (lane >> 2);
            uint32_t h, l;
            float v0 = fmaxf(d1[m][nt][0] + b1s[c], 0.f);
            float v1 = fmaxf(d1[m][nt][1] + b1s[c + 1], 0.f);
            split2(v0, v1, h, l);
            *(uint32_t*)(sm + offAhi + (R * 136 + c) * 2) = h;
            *(uint32_t*)(sm + offAlo + (R * 136 + c) * 2) = l;
            float v2 = fmaxf(d1[m][nt][2] + b1s[c], 0.f);
            float v3 = fmaxf(d1[m][nt][3] + b1s[c + 1], 0.f);
            split2(v2, v3, h, l);
            *(uint32_t*)(sm + offAhi + ((R + 8) * 136 + c) * 2) = h;
            *(uint32_t*)(sm + offAlo + ((R + 8) * 136 + c) * 2) = l;
        }
    __syncthreads();   // H complete

    // ---- GEMM2: 64 x 8 per warp, K = 128 ----
    float d2[4][4];
#pragma unroll
    for (int m = 0; m < 4; m++)
#pragma unroll
        for (int j = 0; j < 4; j++) d2[m][j] = 0.f;

    const uint32_t hoff = (uint32_t)(((lane & 15) * 136 + (lane >> 4) * 8) * 2);
    const uint32_t aH  = sbase + offAhi + hoff;
    const uint32_t aHl = sbase + offAlo + hoff;
    const uint4* __restrict__ w2p = W2f + wid * 32 + lane;

#pragma unroll
    for (int kc = 0; kc < 8; kc++) {
        uint32_t ah[4][4], al[4][4];
#pragma unroll
        for (int m = 0; m < 4; m++) {
            LDSM_X4(ah[m], aH  + (uint32_t)(m * 16 * 136 * 2) + kc * 32);
            LDSM_X4(al[m], aHl + (uint32_t)(m * 16 * 136 * 2) + kc * 32);
        }
        uint4 w = __ldg(w2p + kc * 256);
#pragma unroll
        for (int m = 0; m < 4; m++) {
            MMA16816(d2[m], ah[m], w.x, w.y);
            MMA16816(d2[m], ah[m], w.z, w.w);
            MMA16816(d2[m], al[m], w.x, w.y);
        }
    }

    // ---- epi2: D2 + b2 -> fp32 stage (stride 68) ----
    float* sD2 = (float*)(sm + offD2);
#pragma unroll
    for (int m = 0; m < 4; m++) {
        int c = 8 * wid + (lane & 3) * 2;
        int R = 16 * m + (lane >> 2);
        *(float2*)&sD2[R * 68 + c] = make_float2(d2[m][0] + b2s[c], d2[m][1] + b2s[c + 1]);
        *(float2*)&sD2[(R + 8) * 68 + c] = make_float2(d2[m][2] + b2s[c], d2[m][3] + b2s[c + 1]);
    }
}

// ---------------- edge kernel ----------------
extern __shared__ char dsm[];

#define E_AHI  0u
#define E_ALO  27648u
#define E_D2F  55296u
#define E_SMEM 72704

__global__ __launch_bounds__(256, 2)
void edge_tc(const float* __restrict__ x, const int* __restrict__ ei,
             const float* __restrict__ ea, const float* __restrict__ gf,
             const float* __restrict__ b1, const float* __restrict__ b2,
             float* __restrict__ eout, int E, int N, int ntiles)
{
    __shared__ float b1s[128], b2s[64], redbuf[64];
    const int tid = threadIdx.x, wid = tid >> 5, lane = tid & 31;
    const uint32_t sbase = smem_u32(dsm);

    if (tid < 128) b1s[tid] = b1[tid];
    if (tid < 64)  { b2s[tid] = b2[tid]; redbuf[tid] = 0.f; }
    __syncthreads();

    float acc[4] = {0.f, 0.f, 0.f, 0.f};

    for (int t = blockIdx.x; t < ntiles; t += gridDim.x) {
        // ---- gather: 52 float4 per edge -> A hi/lo ----
        for (int i = tid; i < 64 * 52; i += 256) {
            int e = i / 52, c4 = i % 52;
            int ge = t * 64 + e;
            float4 v = make_float4(0.f, 0.f, 0.f, 0.f);
            if (ge < E) {
                if (c4 < 4) v = ((const float4*)gf)[c4];
                else if (c4 < 20) {
                    int r = ei[ge]; r = min(max(r, 0), N - 1);
                    v = ((const float4*)(x + (size_t)r * 64))[c4 - 4];
                } else if (c4 < 36) {
                    int c = ei[E + ge]; c = min(max(c, 0), N - 1);
                    v = ((const float4*)(x + (size_t)c * 64))[c4 - 20];
                } else
                    v = ((const float4*)(ea + (size_t)ge * 64))[c4 - 36];
            }
            uint32_t h0, l0, h1, l1;
            split2(v.x, v.y, h0, l0);
            split2(v.z, v.w, h1, l1);
            uint32_t off = (uint32_t)(e * 216 + c4 * 4) * 2;
            *(uint2*)(dsm + E_AHI + off) = make_uint2(h0, h1);
            *(uint2*)(dsm + E_ALO + off) = make_uint2(l0, l1);
        }
        __syncthreads();

        tile_mlp<216, 13>(dsm, sbase, E_AHI, E_ALO, E_D2F, g_w1f, g_w2f,
                          b1s, b2s, wid, lane);
        __syncthreads();

        // ---- scatter ----
        const float* sD2 = (const float*)(dsm + E_D2F);
#pragma unroll
        for (int i = 0; i < 4; i++) {
            int row = i * 16 + (tid >> 4);
            int ge = t * 64 + row;
            if (ge < E) {
                int r = ei[ge]; r = min(max(r, 0), N - 1);
                int c4 = (tid & 15) * 4;
                float4 v = *(const float4*)&sD2[row * 68 + c4];
                *(float4*)(eout + (size_t)ge * 64 + c4) = v;
                redv4(g_segsum + (size_t)r * 64 + c4, v.x, v.y, v.z, v.w);
                if ((tid & 15) == 0) atomicAdd(&g_cnt[r], 1.f);
                acc[0] += v.x; acc[1] += v.y; acc[2] += v.z; acc[3] += v.w;
            }
        }
        __syncthreads();
    }
#pragma unroll
    for (int j = 0; j < 4; j++) atomicAdd(&redbuf[(tid & 15) * 4 + j], acc[j]);
    __syncthreads();
    if (tid < 64) atomicAdd(&g_esum[tid], redbuf[tid]);
}

// ---------------- node kernel ----------------
#define N_AHI  0u
#define N_ALO  19456u
#define N_D2F  38912u
#define N_SMEM 56320

__global__ __launch_bounds__(256, 2)
void node_tc(const float* __restrict__ x, const float* __restrict__ gf,
             const float* __restrict__ b1, const float* __restrict__ b2,
             float* __restrict__ nout, int N, int ntiles)
{
    __shared__ float b1s[128], b2s[64], redbuf[64];
    const int tid = threadIdx.x, wid = tid >> 5, lane = tid & 31;
    const uint32_t sbase = smem_u32(dsm);

    if (tid < 128) b1s[tid] = b1[tid];
    if (tid < 64)  { b2s[tid] = b2[tid]; redbuf[tid] = 0.f; }
    __syncthreads();

    float acc[4] = {0.f, 0.f, 0.f, 0.f};

    for (int t = blockIdx.x; t < ntiles; t += gridDim.x) {
        for (int i = tid; i < 64 * 36; i += 256) {
            int e = i / 36, c4 = i % 36;
            int n = t * 64 + e;
            float4 v = make_float4(0.f, 0.f, 0.f, 0.f);
            if (n < N) {
                if (c4 < 4) v = ((const float4*)gf)[c4];
                else if (c4 < 20)
                    v = ((const float4*)(x + (size_t)n * 64))[c4 - 4];
                else {
                    float4 s = ((const float4*)(g_segsum + (size_t)n * 64))[c4 - 20];
                    float inv = 1.0f / fmaxf(g_cnt[n], 1.0f);
                    v = make_float4(s.x * inv, s.y * inv, s.z * inv, s.w * inv);
                }
            }
            uint32_t h0, l0, h1, l1;
            split2(v.x, v.y, h0, l0);
            split2(v.z, v.w, h1, l1);
            uint32_t off = (uint32_t)(e * 152 + c4 * 4) * 2;
            *(uint2*)(dsm + N_AHI + off) = make_uint2(h0, h1);
            *(uint2*)(dsm + N_ALO + off) = make_uint2(l0, l1);
        }
        __syncthreads();

        tile_mlp<152, 9>(dsm, sbase, N_AHI, N_ALO, N_D2F, g_wn1f, g_wn2f,
                         b1s, b2s, wid, lane);
        __syncthreads();

        const float* sD2 = (const float*)(dsm + N_D2F);
#pragma unroll
        for (int i = 0; i < 4; i++) {
            int row = i * 16 + (tid >> 4);
            int n = t * 64 + row;
            if (n < N) {
                int c4 = (tid & 15) * 4;
                float4 v = *(const float4*)&sD2[row * 68 + c4];
                *(float4*)(nout + (size_t)n * 64 + c4) = v;
                acc[0] += v.x; acc[1] += v.y; acc[2] += v.z; acc[3] += v.w;
            }
        }
        __syncthreads();
    }
#pragma unroll
    for (int j = 0; j < 4; j++) atomicAdd(&redbuf[(tid & 15) * 4 + j], acc[j]);
    __syncthreads();
    if (tid < 64) atomicAdd(&g_nsum[tid], redbuf[tid]);
}

// ---------------- global kernel ----------------
__global__ void global_kernel(const float* __restrict__ g,
                              const float* __restrict__ Wg1, const float* __restrict__ bg1,
                              const float* __restrict__ Wg2, const float* __restrict__ bg2,
                              float* __restrict__ out, int N, int E)
{
    __shared__ float in[144], h[128];
    int t = threadIdx.x;
    if (t < 64)       in[t] = g_nsum[t] / (float)N;
    else if (t < 128) in[t] = g_esum[t - 64] / (float)E;
    else if (t < 144) in[t] = g[t - 128];
    __syncthreads();
    if (t < 128) {
        float s = bg1[t];
        for (int k = 0; k < 144; k++) s += in[k] * Wg1[(size_t)k * 128 + t];
        h[t] = fmaxf(s, 0.f);
    }
    __syncthreads();
    if (t < 16) {
        float s = bg2[t];
        for (int k = 0; k < 128; k++) s += h[k] * Wg2[(size_t)k * 16 + t];
        out[t] = s;
    }
}

// ---------------- launch ----------------
extern "C" void kernel_launch(void* const* d_in, const int* in_sizes, int n_in,
                              void* d_out, int out_size)
{
    const float* x   = (const float*)d_in[0];
    const int*   ei  = (const int*)d_in[1];
    const float* ea  = (const float*)d_in[2];
    const float* g   = (const float*)d_in[3];
    const float* We1 = (const float*)d_in[4];
    const float* be1 = (const float*)d_in[5];
    const float* We2 = (const float*)d_in[6];
    const float* be2 = (const float*)d_in[7];
    const float* Wn1 = (const float*)d_in[8];
    const float* bn1 = (const float*)d_in[9];
    const float* Wn2 = (const float*)d_in[10];
    const float* bn2 = (const float*)d_in[11];
    const float* Wg1 = (const float*)d_in[12];
    const float* bg1 = (const float*)d_in[13];
    const float* Wg2 = (const float*)d_in[14];
    const float* bg2 = (const float*)d_in[15];

    int N = in_sizes[0] / 64;
    int E = in_sizes[1] / 2;
    float* eout = (float*)d_out;
    float* nout = eout + (size_t)E * 64;
    float* gout = nout + (size_t)N * 64;

    cudaFuncSetAttribute(edge_tc, cudaFuncAttributeMaxDynamicSharedMemorySize, E_SMEM);
    cudaFuncSetAttribute(node_tc, cudaFuncAttributeMaxDynamicSharedMemorySize, N_SMEM);

    zero_kernel<<<(N * 16 + 255) / 256, 256>>>(N);
    prep_weights<<<60, 256>>>(We1, We2, Wn1, Wn2);

    int etiles = (E + 63) / 64;
    int ntl    = (N + 63) / 64;
    edge_tc<<<296, 256, E_SMEM>>>(x, ei, ea, g, be1, be2, eout, E, N, etiles);
    node_tc<<<296, 256, N_SMEM>>>(x, g, bn1, bn2, nout, N, ntl);
    global_kernel<<<1, 160>>>(g, Wg1, bg1, Wg2, bg2, gout, N, E);
}

// round 7
// speedup vs baseline: 3.3665x; 1.2014x over previous
#include <cuda_runtime.h>
#include <cuda_bf16.h>
#include <stdint.h>
#include <math.h>

#define NMAX 100000

__device__ __align__(16) float g_segsum[(size_t)NMAX * 64];
__device__ float g_cnt[NMAX];
__device__ float g_esum[64];
__device__ float g_nsum[64];

// weights in MMA-fragment order: uint4 = {hi.b0, hi.b1, lo.b0, lo.b1}, [kc][nt8][lane]
__device__ __align__(16) uint4 g_w1f[13 * 16 * 32];
__device__ __align__(16) uint4 g_w2f[8 * 8 * 32];
__device__ __align__(16) uint4 g_wn1f[9 * 16 * 32];
__device__ __align__(16) uint4 g_wn2f[8 * 8 * 32];

// ---------------- helpers ----------------
__device__ __forceinline__ uint32_t smem_u32(const void* p) {
    uint32_t a;
    asm("{ .reg .u64 t; cvta.to.shared.u64 t, %1; cvt.u32.u64 %0, t; }" : "=r"(a) : "l"(p));
    return a;
}
#define LDSM_X4(r, a) asm volatile( \
    "ldmatrix.sync.aligned.m8n8.x4.shared.b16 {%0,%1,%2,%3}, [%4];" \
    : "=r"((r)[0]), "=r"((r)[1]), "=r"((r)[2]), "=r"((r)[3]) : "r"(a))
#define MMA16816(d, a, b0, b1) asm volatile( \
    "mma.sync.aligned.m16n8k16.row.col.f32.bf16.bf16.f32 " \
    "{%0,%1,%2,%3}, {%4,%5,%6,%7}, {%8,%9}, {%0,%1,%2,%3};" \
    : "+f"((d)[0]), "+f"((d)[1]), "+f"((d)[2]), "+f"((d)[3]) \
    : "r"((a)[0]), "r"((a)[1]), "r"((a)[2]), "r"((a)[3]), "r"(b0), "r"(b1))
#define BARC(id) asm volatile("bar.sync %0, 256;" :: "r"(id) : "memory")

__device__ __forceinline__ void mbar_init(uint32_t m, uint32_t c) {
    asm volatile("mbarrier.init.shared.b64 [%0], %1;" :: "r"(m), "r"(c) : "memory");
}
__device__ __forceinline__ void mbar_arrive(uint32_t m) {
    asm volatile("mbarrier.arrive.shared.b64 _, [%0];" :: "r"(m) : "memory");
}
__device__ __forceinline__ void mbar_wait(uint32_t m, int ph) {
    asm volatile("{ .reg .pred P;\nLW%=: mbarrier.try_wait.parity.acquire.cta.shared::cta.b64 P, [%0], %1, 0x989680;\n@P bra LD%=;\nbra LW%=;\nLD%=: }"
                 :: "r"(m), "r"(ph) : "memory");
}
__device__ __forceinline__ void split2(float v0, float v1, uint32_t& h, uint32_t& l) {
    asm("cvt.rn.bf16x2.f32 %0, %1, %2;" : "=r"(h) : "f"(v1), "f"(v0));
    float h0 = __uint_as_float(h << 16);
    float h1 = __uint_as_float(h & 0xffff0000u);
    asm("cvt.rn.bf16x2.f32 %0, %1, %2;" : "=r"(l) : "f"(v1 - h1), "f"(v0 - h0));
}
__device__ __forceinline__ void redv4(float* p, float a, float b, float c, float d) {
    asm volatile("{ .reg .u64 q; cvta.to.global.u64 q, %0;\n"
                 "red.global.add.v4.f32 [q], {%1,%2,%3,%4}; }"
                 :: "l"(p), "f"(a), "f"(b), "f"(c), "f"(d) : "memory");
}

// ---------------- setup ----------------
__global__ void zero_kernel(int N) {
    size_t i = (size_t)blockIdx.x * blockDim.x + threadIdx.x;
    if (i < (size_t)N * 16) ((float4*)g_segsum)[i] = make_float4(0.f, 0.f, 0.f, 0.f);
    if (i < (size_t)N) g_cnt[i] = 0.f;
    if (i < 64) { g_esum[i] = 0.f; g_nsum[i] = 0.f; }
}
__device__ __forceinline__ uint4 mkfrag(const float* W, int ncols, int kc, int nt8, int lane) {
    int k0 = kc * 16 + 2 * (lane & 3);
    int n  = nt8 * 8 + (lane >> 2);
    float w00 = W[(size_t)k0 * ncols + n];
    float w01 = W[(size_t)(k0 + 1) * ncols + n];
    float w10 = W[(size_t)(k0 + 8) * ncols + n];
    float w11 = W[(size_t)(k0 + 9) * ncols + n];
    uint32_t h0, l0, h1, l1;
    split2(w00, w01, h0, l0);
    split2(w10, w11, h1, l1);
    return make_uint4(h0, h1, l0, l1);
}
__global__ void prep_weights(const float* We1, const float* We2,
                             const float* Wn1, const float* Wn2) {
    int i = blockIdx.x * blockDim.x + threadIdx.x;
    if (i < 13 * 16 * 32) { int kc = i >> 9, r = i & 511; g_w1f[i] = mkfrag(We1, 128, kc, r >> 5, r & 31); return; }
    i -= 13 * 16 * 32;
    if (i < 8 * 8 * 32)   { int kc = i >> 8, r = i & 255; g_w2f[i] = mkfrag(We2, 64, kc, r >> 5, r & 31); return; }
    i -= 8 * 8 * 32;
    if (i < 9 * 16 * 32)  { int kc = i >> 9, r = i & 511; g_wn1f[i] = mkfrag(Wn1, 128, kc, r >> 5, r & 31); return; }
    i -= 9 * 16 * 32;
    if (i < 8 * 8 * 32)   { int kc = i >> 8, r = i & 255; g_wn2f[i] = mkfrag(Wn2, 64, kc, r >> 5, r & 31); }
}

// ---------------- consumer MLP on one 64-row tile ----------------
// A slot (bf16 hi/lo, stride SA), H separate (stride 136), D2 fp32 (stride 68).
template<int SA, int KC1>
__device__ __forceinline__ void tile_mlp(char* sm, uint32_t sbase,
    uint32_t offAhi, uint32_t offAlo, uint32_t offHhi, uint32_t offHlo, uint32_t offD2,
    const uint4* __restrict__ W1f, const uint4* __restrict__ W2f,
    const float* b1s, const float* b2s, int wid, int lane, uint32_t emptyAddr)
{
    float d1[4][2][4];
#pragma unroll
    for (int m = 0; m < 4; m++)
#pragma unroll
        for (int nt = 0; nt < 2; nt++)
#pragma unroll
            for (int j = 0; j < 4; j++) d1[m][nt][j] = 0.f;

    const uint32_t aoff = (uint32_t)(((lane & 15) * SA + (lane >> 4) * 8) * 2);
    const uint32_t aAh = sbase + offAhi + aoff;
    const uint32_t aAl = sbase + offAlo + aoff;
    const uint4* __restrict__ w1p = W1f + (2 * wid) * 32 + lane;

    for (int kc = 0; kc < KC1; kc++) {
        uint32_t ah[4][4], al[4][4];
#pragma unroll
        for (int m = 0; m < 4; m++) {
            LDSM_X4(ah[m], aAh + (uint32_t)(m * 16 * SA * 2) + kc * 32);
            LDSM_X4(al[m], aAl + (uint32_t)(m * 16 * SA * 2) + kc * 32);
        }
        uint4 w0 = __ldg(w1p + kc * 512);
        uint4 w1 = __ldg(w1p + kc * 512 + 32);
#pragma unroll
        for (int m = 0; m < 4; m++) {
            MMA16816(d1[m][0], ah[m], w0.x, w0.y);
            MMA16816(d1[m][0], ah[m], w0.z, w0.w);
            MMA16816(d1[m][0], al[m], w0.x, w0.y);
            MMA16816(d1[m][1], ah[m], w1.x, w1.y);
            MMA16816(d1[m][1], ah[m], w1.z, w1.w);
            MMA16816(d1[m][1], al[m], w1.x, w1.y);
        }
    }
    mbar_arrive(emptyAddr);   // A slot free -> producer may refill

    // epi1: H = relu(D1 + b1) -> bf16 hi/lo, stride 136
#pragma unroll
    for (int m = 0; m < 4; m++)
#pragma unroll
        for (int nt = 0; nt < 2; nt++) {
            int c = 16 * wid + 8 * nt + (lane & 3) * 2;
            int R = 16 * m + (lane >> 2);
            uint32_t h, l;
            float v0 = fmaxf(d1[m][nt][0] + b1s[c], 0.f);
            float v1 = fmaxf(d1[m][nt][1] + b1s[c + 1], 0.f);
            split2(v0, v1, h, l);
            *(uint32_t*)(sm + offHhi + (R * 136 + c) * 2) = h;
            *(uint32_t*)(sm + offHlo + (R * 136 + c) * 2) = l;
            float v2 = fmaxf(d1[m][nt][2] + b1s[c], 0.f);
            float v3 = fmaxf(d1[m][nt][3] + b1s[c + 1], 0.f);
            split2(v2, v3, h, l);
            *(uint32_t*)(sm + offHhi + ((R + 8) * 136 + c) * 2) = h;
            *(uint32_t*)(sm + offHlo + ((R + 8) * 136 + c) * 2) = l;
        }
    BARC(1);   // H complete (consumers only)

    // GEMM2: 64x8 per warp, K=128
    float d2[4][4];
#pragma unroll
    for (int m = 0; m < 4; m++)
#pragma unroll
        for (int j = 0; j < 4; j++) d2[m][j] = 0.f;

    const uint32_t hoff = (uint32_t)(((lane & 15) * 136 + (lane >> 4) * 8) * 2);
    const uint32_t aH  = sbase + offHhi + hoff;
    const uint32_t aHl = sbase + offHlo + hoff;
    const uint4* __restrict__ w2p = W2f + wid * 32 + lane;

#pragma unroll
    for (int kc = 0; kc < 8; kc++) {
        uint32_t ah[4][4], al[4][4];
#pragma unroll
        for (int m = 0; m < 4; m++) {
            LDSM_X4(ah[m], aH  + (uint32_t)(m * 16 * 136 * 2) + kc * 32);
            LDSM_X4(al[m], aHl + (uint32_t)(m * 16 * 136 * 2) + kc * 32);
        }
        uint4 w = __ldg(w2p + kc * 256);
#pragma unroll
        for (int m = 0; m < 4; m++) {
            MMA16816(d2[m], ah[m], w.x, w.y);
            MMA16816(d2[m], ah[m], w.z, w.w);
            MMA16816(d2[m], al[m], w.x, w.y);
        }
    }

    // epi2: D2 + b2 -> fp32 stage (stride 68)
    float* sD2 = (float*)(sm + offD2);
#pragma unroll
    for (int m = 0; m < 4; m++) {
        int c = 8 * wid + (lane & 3) * 2;
        int R = 16 * m + (lane >> 2);
        *(float2*)&sD2[R * 68 + c] = make_float2(d2[m][0] + b2s[c], d2[m][1] + b2s[c + 1]);
        *(float2*)&sD2[(R + 8) * 68 + c] = make_float2(d2[m][2] + b2s[c], d2[m][3] + b2s[c + 1]);
    }
    BARC(2);   // D2 complete
}

// ---------------- edge kernel ----------------
extern __shared__ char dsm[];

#define E_SLOT  55296u
#define E_ALOD  27648u
#define E_HHI   110592u
#define E_HLO   128000u
#define E_D2F   145408u
#define E_SMEM  162816

__global__ __launch_bounds__(384, 1)
void edge_tc(const float* __restrict__ x, const int* __restrict__ ei,
             const float* __restrict__ ea, const float* __restrict__ gf,
             const float* __restrict__ b1, const float* __restrict__ b2,
             float* __restrict__ eout, int E, int N, int ntiles)
{
    __shared__ float b1s[128], b2s[64], redbuf[64];
    __shared__ __align__(16) unsigned long long s_bar[4];  // full0,full1,empty0,empty1
    const int tid = threadIdx.x, wid = tid >> 5, lane = tid & 31;
    const uint32_t sbase = smem_u32(dsm);
    const uint32_t bfull = smem_u32(&s_bar[0]), bempty = smem_u32(&s_bar[2]);

    if (tid < 128) b1s[tid] = b1[tid];
    if (tid < 64)  { b2s[tid] = b2[tid]; redbuf[tid] = 0.f; }
    if (tid == 0) {
        mbar_init(bfull, 128); mbar_init(bfull + 8, 128);
        mbar_init(bempty, 256); mbar_init(bempty + 8, 256);
    }
    __syncthreads();

    if (tid < 256) {  // ---- consumers ----
        float acc[4] = {0.f, 0.f, 0.f, 0.f};
        int i = 0;
        for (int t = blockIdx.x; t < ntiles; t += gridDim.x, i++) {
            int s = i & 1, ph = (i >> 1) & 1;
            mbar_wait(bfull + 8 * s, ph);
            tile_mlp<216, 13>(dsm, sbase, s * E_SLOT, s * E_SLOT + E_ALOD,
                              E_HHI, E_HLO, E_D2F, g_w1f, g_w2f,
                              b1s, b2s, wid, lane, bempty + 8 * s);
            const float* sD2 = (const float*)(dsm + E_D2F);
#pragma unroll
            for (int k = 0; k < 4; k++) {
                int row = k * 16 + (tid >> 4);
                int ge = t * 64 + row;
                if (ge < E) {
                    int r = ei[ge]; r = min(max(r, 0), N - 1);
                    int c4 = (tid & 15) * 4;
                    float4 v = *(const float4*)&sD2[row * 68 + c4];
                    *(float4*)(eout + (size_t)ge * 64 + c4) = v;
                    redv4(g_segsum + (size_t)r * 64 + c4, v.x, v.y, v.z, v.w);
                    if ((tid & 15) == 0) atomicAdd(&g_cnt[r], 1.f);
                    acc[0] += v.x; acc[1] += v.y; acc[2] += v.z; acc[3] += v.w;
                }
            }
        }
#pragma unroll
        for (int j = 0; j < 4; j++) atomicAdd(&redbuf[(tid & 15) * 4 + j], acc[j]);
        BARC(3);
        if (tid < 64) atomicAdd(&g_esum[tid], redbuf[tid]);
    } else {  // ---- producers ----
        const int tid2 = tid - 256;
        const int e = tid2 & 63;
        const int half = tid2 >> 6;
        int i = 0;
        for (int t = blockIdx.x; t < ntiles; t += gridDim.x, i++) {
            int s = i & 1;
            if (i >= 2) mbar_wait(bempty + 8 * s, ((i >> 1) + 1) & 1);
            int ge = t * 64 + e;
            bool v = ge < E;
            int r = 0, c = 0;
            if (v) {
                r = ei[ge]; c = ei[E + ge];
                r = min(max(r, 0), N - 1); c = min(max(c, 0), N - 1);
            }
            char* sb = dsm + s * E_SLOT;
            const float4* g4 = (const float4*)gf;
            const float4* xr = (const float4*)(x + (size_t)r * 64);
            const float4* xc = (const float4*)(x + (size_t)c * 64);
            const float4* e4 = (const float4*)(ea + (size_t)ge * 64);
#pragma unroll
            for (int b = 0; b < 2; b++) {
                float4 vv[13];
#pragma unroll
                for (int j = 0; j < 13; j++) {
                    int c4 = half * 26 + b * 13 + j;
                    float4 w = make_float4(0.f, 0.f, 0.f, 0.f);
                    if (v) {
                        if (c4 < 4) w = g4[c4];
                        else if (c4 < 20) w = xr[c4 - 4];
                        else if (c4 < 36) w = xc[c4 - 20];
                        else w = e4[c4 - 36];
                    }
                    vv[j] = w;
                }
#pragma unroll
                for (int j = 0; j < 13; j++) {
                    int c4 = half * 26 + b * 13 + j;
                    uint32_t h0, l0, h1, l1;
                    split2(vv[j].x, vv[j].y, h0, l0);
                    split2(vv[j].z, vv[j].w, h1, l1);
                    uint32_t off = (uint32_t)(e * 216 + c4 * 4) * 2;
                    *(uint2*)(sb + off) = make_uint2(h0, h1);
                    *(uint2*)(sb + E_ALOD + off) = make_uint2(l0, l1);
                }
            }
            mbar_arrive(bfull + 8 * s);
        }
    }
}

// ---------------- node kernel ----------------
#define N_SLOT  38912u
#define N_ALOD  19456u
#define N_HHI   77824u
#define N_HLO   95232u
#define N_D2F   112640u
#define N_SMEM  130048

__global__ __launch_bounds__(384, 1)
void node_tc(const float* __restrict__ x, const float* __restrict__ gf,
             const float* __restrict__ b1, const float* __restrict__ b2,
             float* __restrict__ nout, int N, int ntiles)
{
    __shared__ float b1s[128], b2s[64], redbuf[64];
    __shared__ __align__(16) unsigned long long s_bar[4];
    const int tid = threadIdx.x, wid = tid >> 5, lane = tid & 31;
    const uint32_t sbase = smem_u32(dsm);
    const uint32_t bfull = smem_u32(&s_bar[0]), bempty = smem_u32(&s_bar[2]);

    if (tid < 128) b1s[tid] = b1[tid];
    if (tid < 64)  { b2s[tid] = b2[tid]; redbuf[tid] = 0.f; }
    if (tid == 0) {
        mbar_init(bfull, 128); mbar_init(bfull + 8, 128);
        mbar_init(bempty, 256); mbar_init(bempty + 8, 256);
    }
    __syncthreads();

    if (tid < 256) {  // consumers
        float acc[4] = {0.f, 0.f, 0.f, 0.f};
        int i = 0;
        for (int t = blockIdx.x; t < ntiles; t += gridDim.x, i++) {
            int s = i & 1, ph = (i >> 1) & 1;
            mbar_wait(bfull + 8 * s, ph);
            tile_mlp<152, 9>(dsm, sbase, s * N_SLOT, s * N_SLOT + N_ALOD,
                             N_HHI, N_HLO, N_D2F, g_wn1f, g_wn2f,
                             b1s, b2s, wid, lane, bempty + 8 * s);
            const float* sD2 = (const float*)(dsm + N_D2F);
#pragma unroll
            for (int k = 0; k < 4; k++) {
                int row = k * 16 + (tid >> 4);
                int n = t * 64 + row;
                if (n < N) {
                    int c4 = (tid & 15) * 4;
                    float4 v = *(const float4*)&sD2[row * 68 + c4];
                    *(float4*)(nout + (size_t)n * 64 + c4) = v;
                    acc[0] += v.x; acc[1] += v.y; acc[2] += v.z; acc[3] += v.w;
                }
            }
        }
#pragma unroll
        for (int j = 0; j < 4; j++) atomicAdd(&redbuf[(tid & 15) * 4 + j], acc[j]);
        BARC(3);
        if (tid < 64) atomicAdd(&g_nsum[tid], redbuf[tid]);
    } else {  // producers
        const int tid2 = tid - 256;
        const int e = tid2 & 63;
        const int half = tid2 >> 6;
        int i = 0;
        for (int t = blockIdx.x; t < ntiles; t += gridDim.x, i++) {
            int s = i & 1;
            if (i >= 2) mbar_wait(bempty + 8 * s, ((i >> 1) + 1) & 1);
            int n = t * 64 + e;
            bool v = n < N;
            float inv = 1.f;
            if (v && half == 1) inv = 1.0f / fmaxf(g_cnt[n], 1.0f);
            char* sb = dsm + s * N_SLOT;
            const float4* g4 = (const float4*)gf;
            const float4* xn = (const float4*)(x + (size_t)n * 64);
            const float4* sg = (const float4*)(g_segsum + (size_t)n * 64);
#pragma unroll
            for (int b = 0; b < 2; b++) {
                float4 vv[9];
#pragma unroll
                for (int j = 0; j < 9; j++) {
                    int c4 = half * 18 + b * 9 + j;
                    float4 w = make_float4(0.f, 0.f, 0.f, 0.f);
                    if (v) {
                        if (c4 < 4) w = g4[c4];
                        else if (c4 < 20) w = xn[c4 - 4];
                        else {
                            float4 q = sg[c4 - 20];
                            w = make_float4(q.x * inv, q.y * inv, q.z * inv, q.w * inv);
                        }
                    }
                    vv[j] = w;
                }
#pragma unroll
                for (int j = 0; j < 9; j++) {
                    int c4 = half * 18 + b * 9 + j;
                    uint32_t h0, l0, h1, l1;
                    split2(vv[j].x, vv[j].y, h0, l0);
                    split2(vv[j].z, vv[j].w, h1, l1);
                    uint32_t off = (uint32_t)(e * 152 + c4 * 4) * 2;
                    *(uint2*)(sb + off) = make_uint2(h0, h1);
                    *(uint2*)(sb + N_ALOD + off) = make_uint2(l0, l1);
                }
            }
            mbar_arrive(bfull + 8 * s);
        }
    }
}

// ---------------- global kernel ----------------
__global__ void global_kernel(const float* __restrict__ g,
                              const float* __restrict__ Wg1, const float* __restrict__ bg1,
                              const float* __restrict__ Wg2, const float* __restrict__ bg2,
                              float* __restrict__ out, int N, int E)
{
    __shared__ float in[144], h[128];
    int t = threadIdx.x;
    if (t < 64)       in[t] = g_nsum[t] / (float)N;
    else if (t < 128) in[t] = g_esum[t - 64] / (float)E;
    else if (t < 144) in[t] = g[t - 128];
    __syncthreads();
    if (t < 128) {
        float s = bg1[t];
        for (int k = 0; k < 144; k++) s += in[k] * Wg1[(size_t)k * 128 + t];
        h[t] = fmaxf(s, 0.f);
    }
    __syncthreads();
    if (t < 16) {
        float s = bg2[t];
        for (int k = 0; k < 128; k++) s += h[k] * Wg2[(size_t)k * 16 + t];
        out[t] = s;
    }
}

// ---------------- launch ----------------
extern "C" void kernel_launch(void* const* d_in, const int* in_sizes, int n_in,
                              void* d_out, int out_size)
{
    const float* x   = (const float*)d_in[0];
    const int*   ei  = (const int*)d_in[1];
    const float* ea  = (const float*)d_in[2];
    const float* g   = (const float*)d_in[3];
    const float* We1 = (const float*)d_in[4];
    const float* be1 = (const float*)d_in[5];
    const float* We2 = (const float*)d_in[6];
    const float* be2 = (const float*)d_in[7];
    const float* Wn1 = (const float*)d_in[8];
    const float* bn1 = (const float*)d_in[9];
    const float* Wn2 = (const float*)d_in[10];
    const float* bn2 = (const float*)d_in[11];
    const float* Wg1 = (const float*)d_in[12];
    const float* bg1 = (const float*)d_in[13];
    const float* Wg2 = (const float*)d_in[14];
    const float* bg2 = (const float*)d_in[15];

    int N = in_sizes[0] / 64;
    int E = in_sizes[1] / 2;
    float* eout = (float*)d_out;
    float* nout = eout + (size_t)E * 64;
    float* gout = nout + (size_t)N * 64;

    cudaFuncSetAttribute(edge_tc, cudaFuncAttributeMaxDynamicSharedMemorySize, E_SMEM);
    cudaFuncSetAttribute(node_tc, cudaFuncAttributeMaxDynamicSharedMemorySize, N_SMEM);

    zero_kernel<<<(N * 16 + 255) / 256, 256>>>(N);
    prep_weights<<<60, 256>>>(We1, We2, Wn1, Wn2);

    int etiles = (E + 63) / 64;
    int ntl    = (N + 63) / 64;
    edge_tc<<<148, 384, E_SMEM>>>(x, ei, ea, g, be1, be2, eout, E, N, etiles);
    node_tc<<<148, 384, N_SMEM>>>(x, g, bn1, bn2, nout, N, ntl);
    global_kernel<<<1, 160>>>(g, Wg1, bg1, Wg2, bg2, gout, N, E);
}

// round 8
// speedup vs baseline: 3.6659x; 1.0889x over previous
#include <cuda_runtime.h>
#include <cuda_fp16.h>
#include <stdint.h>
#include <math.h>

#define NMAX 100000

__device__ __align__(16) float g_segsum[(size_t)NMAX * 64];
__device__ float g_cnt[NMAX];
__device__ float g_esum[64];
__device__ float g_nsum[64];

// fp16 weights in MMA-fragment order: uint4 = {hi.b0, hi.b1, lo.b0, lo.b1}, [kc][nt8][lane]
__device__ __align__(16) uint4 g_w1f[13 * 16 * 32];
__device__ __align__(16) uint4 g_w2f[8 * 8 * 32];
__device__ __align__(16) uint4 g_wn1f[9 * 16 * 32];
__device__ __align__(16) uint4 g_wn2f[8 * 8 * 32];

// ---------------- helpers ----------------
__device__ __forceinline__ uint32_t smem_u32(const void* p) {
    uint32_t a;
    asm("{ .reg .u64 t; cvta.to.shared.u64 t, %1; cvt.u32.u64 %0, t; }" : "=r"(a) : "l"(p));
    return a;
}
#define LDSM_X4(r, a) asm volatile( \
    "ldmatrix.sync.aligned.m8n8.x4.shared.b16 {%0,%1,%2,%3}, [%4];" \
    : "=r"((r)[0]), "=r"((r)[1]), "=r"((r)[2]), "=r"((r)[3]) : "r"(a))
#define MMA16816(d, a, b0, b1) asm volatile( \
    "mma.sync.aligned.m16n8k16.row.col.f32.f16.f16.f32 " \
    "{%0,%1,%2,%3}, {%4,%5,%6,%7}, {%8,%9}, {%0,%1,%2,%3};" \
    : "+f"((d)[0]), "+f"((d)[1]), "+f"((d)[2]), "+f"((d)[3]) \
    : "r"((a)[0]), "r"((a)[1]), "r"((a)[2]), "r"((a)[3]), "r"(b0), "r"(b1))
#define BARC128(id) asm volatile("bar.sync %0, 128;" :: "r"(id) : "memory")

__device__ __forceinline__ void mbar_init(uint32_t m, uint32_t c) {
    asm volatile("mbarrier.init.shared.b64 [%0], %1;" :: "r"(m), "r"(c) : "memory");
}
__device__ __forceinline__ void mbar_arrive(uint32_t m) {
    asm volatile("mbarrier.arrive.shared.b64 _, [%0];" :: "r"(m) : "memory");
}
__device__ __forceinline__ void mbar_wait(uint32_t m, int ph) {
    asm volatile("{ .reg .pred P;\nLW%=: mbarrier.try_wait.parity.acquire.cta.shared::cta.b64 P, [%0], %1, 0x989680;\n@P bra LD%=;\nbra LW%=;\nLD%=: }"
                 :: "r"(m), "r"(ph) : "memory");
}
__device__ __forceinline__ void split2h(float v0, float v1, uint32_t& h, uint32_t& l) {
    __half2 H = __floats2half2_rn(v0, v1);
    float2 hf = __half22float2(H);
    __half2 L = __floats2half2_rn(v0 - hf.x, v1 - hf.y);
    h = *(uint32_t*)&H;
    l = *(uint32_t*)&L;
}
__device__ __forceinline__ void redv2(float* p, float a, float b) {
    asm volatile("{ .reg .u64 q; cvta.to.global.u64 q, %0;\n"
                 "red.global.add.v2.f32 [q], {%1,%2}; }"
                 :: "l"(p), "f"(a), "f"(b) : "memory");
}

// ---------------- setup ----------------
__global__ void zero_kernel(int N) {
    size_t i = (size_t)blockIdx.x * blockDim.x + threadIdx.x;
    if (i < (size_t)N * 16) ((float4*)g_segsum)[i] = make_float4(0.f, 0.f, 0.f, 0.f);
    if (i < (size_t)N) g_cnt[i] = 0.f;
    if (i < 64) { g_esum[i] = 0.f; g_nsum[i] = 0.f; }
}
__device__ __forceinline__ uint4 mkfrag(const float* W, int ncols, int kc, int nt8, int lane) {
    int k0 = kc * 16 + 2 * (lane & 3);
    int n  = nt8 * 8 + (lane >> 2);
    float w00 = W[(size_t)k0 * ncols + n];
    float w01 = W[(size_t)(k0 + 1) * ncols + n];
    float w10 = W[(size_t)(k0 + 8) * ncols + n];
    float w11 = W[(size_t)(k0 + 9) * ncols + n];
    uint32_t h0, l0, h1, l1;
    split2h(w00, w01, h0, l0);
    split2h(w10, w11, h1, l1);
    return make_uint4(h0, h1, l0, l1);
}
__global__ void prep_weights(const float* We1, const float* We2,
                             const float* Wn1, const float* Wn2) {
    int i = blockIdx.x * blockDim.x + threadIdx.x;
    if (i < 13 * 16 * 32) { int kc = i >> 9, r = i & 511; g_w1f[i] = mkfrag(We1, 128, kc, r >> 5, r & 31); return; }
    i -= 13 * 16 * 32;
    if (i < 8 * 8 * 32)   { int kc = i >> 8, r = i & 255; g_w2f[i] = mkfrag(We2, 64, kc, r >> 5, r & 31); return; }
    i -= 8 * 8 * 32;
    if (i < 9 * 16 * 32)  { int kc = i >> 9, r = i & 511; g_wn1f[i] = mkfrag(Wn1, 128, kc, r >> 5, r & 31); return; }
    i -= 9 * 16 * 32;
    if (i < 8 * 8 * 32)   { int kc = i >> 8, r = i & 255; g_wn2f[i] = mkfrag(Wn2, 64, kc, r >> 5, r & 31); }
}

// ---------------- consumer MLP on one 64-row tile (4 warps, 32 cols each) ----------------
// A (fp16 hi/lo, byte stride SA2). H fp16 single-stream (stride 272B). d2 returned in regs.
template<int SA2, int KC1>
__device__ __forceinline__ void tile_mlp(char* sm, uint32_t sbase,
    uint32_t offAhi, uint32_t offAlo, uint32_t offH,
    const uint4* __restrict__ W1f, const uint4* __restrict__ W2f,
    const float* b1s, int wid, int lane, uint32_t emptyAddr,
    float (&d2)[4][2][4])
{
    float d1[4][4][4];
#pragma unroll
    for (int m = 0; m < 4; m++)
#pragma unroll
        for (int j = 0; j < 4; j++)
#pragma unroll
            for (int k = 0; k < 4; k++) d1[m][j][k] = 0.f;

    const uint32_t aoff = (uint32_t)((lane & 15) * SA2 + (lane >> 4) * 16);
    const uint32_t aAh = sbase + offAhi + aoff;
    const uint32_t aAl = sbase + offAlo + aoff;
    const uint4* __restrict__ w1p = W1f + 4 * wid * 32 + lane;

    for (int kc = 0; kc < KC1; kc++) {
        uint32_t ah[4][4], al[4][4];
#pragma unroll
        for (int m = 0; m < 4; m++) {
            LDSM_X4(ah[m], aAh + (uint32_t)(m * 16 * SA2) + kc * 32);
            LDSM_X4(al[m], aAl + (uint32_t)(m * 16 * SA2) + kc * 32);
        }
        uint4 w[4];
#pragma unroll
        for (int j = 0; j < 4; j++) w[j] = __ldg(w1p + kc * 512 + j * 32);
#pragma unroll
        for (int m = 0; m < 4; m++)
#pragma unroll
            for (int j = 0; j < 4; j++) {
                MMA16816(d1[m][j], ah[m], w[j].x, w[j].y);
                MMA16816(d1[m][j], ah[m], w[j].z, w[j].w);
                MMA16816(d1[m][j], al[m], w[j].x, w[j].y);
            }
    }
    mbar_arrive(emptyAddr);   // A slot free for producer

    // epi1: H = relu(D1 + b1) -> fp16 hi only, stride 136 halves (272B)
#pragma unroll
    for (int m = 0; m < 4; m++)
#pragma unroll
        for (int j = 0; j < 4; j++) {
            int c = 32 * wid + 8 * j + 2 * (lane & 3);
            int R = 16 * m + (lane >> 2);
            __half2 p0 = __floats2half2_rn(fmaxf(d1[m][j][0] + b1s[c], 0.f),
                                           fmaxf(d1[m][j][1] + b1s[c + 1], 0.f));
            *(__half2*)(sm + offH + (R * 136 + c) * 2) = p0;
            __half2 p1 = __floats2half2_rn(fmaxf(d1[m][j][2] + b1s[c], 0.f),
                                           fmaxf(d1[m][j][3] + b1s[c + 1], 0.f));
            *(__half2*)(sm + offH + ((R + 8) * 136 + c) * 2) = p1;
        }
    BARC128(1);   // H visible to all consumer warps

    // GEMM2: 64x16 per warp, K=128, 2 terms (Hh*W2h + Hh*W2l)
#pragma unroll
    for (int m = 0; m < 4; m++)
#pragma unroll
        for (int j = 0; j < 2; j++)
#pragma unroll
            for (int k = 0; k < 4; k++) d2[m][j][k] = 0.f;

    const uint32_t hoff = (uint32_t)((lane & 15) * 272 + (lane >> 4) * 16);
    const uint32_t aH = sbase + offH + hoff;
    const uint4* __restrict__ w2p = W2f + 2 * wid * 32 + lane;

#pragma unroll
    for (int kc = 0; kc < 8; kc++) {
        uint32_t hh[4][4];
#pragma unroll
        for (int m = 0; m < 4; m++)
            LDSM_X4(hh[m], aH + (uint32_t)(m * 16 * 272) + kc * 32);
        uint4 w0 = __ldg(w2p + kc * 256);
        uint4 w1 = __ldg(w2p + kc * 256 + 32);
#pragma unroll
        for (int m = 0; m < 4; m++) {
            MMA16816(d2[m][0], hh[m], w0.x, w0.y);
            MMA16816(d2[m][0], hh[m], w0.z, w0.w);
            MMA16816(d2[m][1], hh[m], w1.x, w1.y);
            MMA16816(d2[m][1], hh[m], w1.z, w1.w);
        }
    }
    BARC128(1);   // all H reads done -> next tile's epi1 may overwrite H
}

// ---------------- edge kernel ----------------
extern __shared__ char dsm[];

#define E_SA2  432
#define E_SLOT 55296u
#define E_ALOD 27648u
#define E_H    110592u
#define E_SMEM 128000

__global__ __launch_bounds__(384, 1)
void edge_tc(const float* __restrict__ x, const int* __restrict__ ei,
             const float* __restrict__ ea, const float* __restrict__ gf,
             const float* __restrict__ b1, const float* __restrict__ b2,
             float* __restrict__ eout, int E, int N, int ntiles)
{
    __shared__ float b1s[128], b2s[64], redbuf[64];
    __shared__ __align__(16) unsigned long long s_bar[4];
    const int tid = threadIdx.x, wid = tid >> 5, lane = tid & 31;
    const uint32_t sbase = smem_u32(dsm);
    const uint32_t bfull = smem_u32(&s_bar[0]), bempty = smem_u32(&s_bar[2]);

    if (tid < 128) b1s[tid] = b1[tid];
    if (tid < 64)  { b2s[tid] = b2[tid]; redbuf[tid] = 0.f; }
    if (tid == 0) {
        mbar_init(bfull, 256); mbar_init(bfull + 8, 256);
        mbar_init(bempty, 128); mbar_init(bempty + 8, 128);
    }
    __syncthreads();

    if (tid < 128) {  // ---- consumers (4 warps) ----
        float acc[2][2] = {{0.f, 0.f}, {0.f, 0.f}};
        int i = 0;
        for (int t = blockIdx.x; t < ntiles; t += gridDim.x, i++) {
            int s = i & 1, ph = (i >> 1) & 1;
            mbar_wait(bfull + 8 * s, ph);
            float d2[4][2][4];
            tile_mlp<E_SA2, 13>(dsm, sbase, s * E_SLOT, s * E_SLOT + E_ALOD, E_H,
                                g_w1f, g_w2f, b1s, wid, lane, bempty + 8 * s, d2);
            // scatter from regs
#pragma unroll
            for (int m = 0; m < 4; m++) {
                int Rb = 16 * m + (lane >> 2);
#pragma unroll
                for (int h = 0; h < 2; h++) {
                    int row = Rb + 8 * h;
                    int ge = t * 64 + row;
                    if (ge < E) {
                        int r = ei[ge]; r = min(max(r, 0), N - 1);
#pragma unroll
                        for (int j = 0; j < 2; j++) {
                            int c = 16 * wid + 8 * j + 2 * (lane & 3);
                            float v0 = d2[m][j][2 * h]     + b2s[c];
                            float v1 = d2[m][j][2 * h + 1] + b2s[c + 1];
                            *(float2*)(eout + (size_t)ge * 64 + c) = make_float2(v0, v1);
                            redv2(g_segsum + (size_t)r * 64 + c, v0, v1);
                            acc[j][0] += v0; acc[j][1] += v1;
                        }
                        if (wid == 0 && (lane & 3) == 0) atomicAdd(&g_cnt[r], 1.f);
                    }
                }
            }
        }
#pragma unroll
        for (int j = 0; j < 2; j++) {
            atomicAdd(&redbuf[16 * wid + 8 * j + 2 * (lane & 3)], acc[j][0]);
            atomicAdd(&redbuf[16 * wid + 8 * j + 2 * (lane & 3) + 1], acc[j][1]);
        }
        BARC128(2);
        if (tid < 64) atomicAdd(&g_esum[tid], redbuf[tid]);
    } else {  // ---- producers (8 warps, 4 threads/row) ----
        const int pt = tid - 128;
        const int e = pt >> 2, q = pt & 3;
        int i = 0;
        for (int t = blockIdx.x; t < ntiles; t += gridDim.x, i++) {
            int s = i & 1;
            if (i >= 2) mbar_wait(bempty + 8 * s, ((i >> 1) + 1) & 1);
            int ge = t * 64 + e;
            bool v = ge < E;
            int r = 0, c = 0;
            if (v) {
                r = ei[ge]; c = ei[E + ge];
                r = min(max(r, 0), N - 1); c = min(max(c, 0), N - 1);
            }
            char* sb = dsm + s * E_SLOT;
            const float4* g4 = (const float4*)gf;
            const float4* xr = (const float4*)(x + (size_t)r * 64);
            const float4* xc = (const float4*)(x + (size_t)c * 64);
            const float4* e4 = (const float4*)(ea + (size_t)ge * 64);
            float4 vv[13];
#pragma unroll
            for (int j = 0; j < 13; j++) {
                int c4 = q + 4 * j;
                float4 w = make_float4(0.f, 0.f, 0.f, 0.f);
                if (v) {
                    if (c4 < 4) w = g4[c4];
                    else if (c4 < 20) w = xr[c4 - 4];
                    else if (c4 < 36) w = xc[c4 - 20];
                    else w = e4[c4 - 36];
                }
                vv[j] = w;
            }
#pragma unroll
            for (int j = 0; j < 13; j++) {
                int c4 = q + 4 * j;
                uint32_t h0, l0, h1, l1;
                split2h(vv[j].x, vv[j].y, h0, l0);
                split2h(vv[j].z, vv[j].w, h1, l1);
                uint32_t off = (uint32_t)(e * E_SA2 + c4 * 8);
                *(uint2*)(sb + off) = make_uint2(h0, h1);
                *(uint2*)(sb + E_ALOD + off) = make_uint2(l0, l1);
            }
            mbar_arrive(bfull + 8 * s);
        }
    }
}

// ---------------- node kernel ----------------
#define N_SA2  304
#define N_SLOT 38912u
#define N_ALOD 19456u
#define N_H    77824u
#define N_SMEM 95232

__global__ __launch_bounds__(384, 1)
void node_tc(const float* __restrict__ x, const float* __restrict__ gf,
             const float* __restrict__ b1, const float* __restrict__ b2,
             float* __restrict__ nout, int N, int ntiles)
{
    __shared__ float b1s[128], b2s[64], redbuf[64];
    __shared__ __align__(16) unsigned long long s_bar[4];
    const int tid = threadIdx.x, wid = tid >> 5, lane = tid & 31;
    const uint32_t sbase = smem_u32(dsm);
    const uint32_t bfull = smem_u32(&s_bar[0]), bempty = smem_u32(&s_bar[2]);

    if (tid < 128) b1s[tid] = b1[tid];
    if (tid < 64)  { b2s[tid] = b2[tid]; redbuf[tid] = 0.f; }
    if (tid == 0) {
        mbar_init(bfull, 256); mbar_init(bfull + 8, 256);
        mbar_init(bempty, 128); mbar_init(bempty + 8, 128);
    }
    __syncthreads();

    if (tid < 128) {  // consumers
        float acc[2][2] = {{0.f, 0.f}, {0.f, 0.f}};
        int i = 0;
        for (int t = blockIdx.x; t < ntiles; t += gridDim.x, i++) {
            int s = i & 1, ph = (i >> 1) & 1;
            mbar_wait(bfull + 8 * s, ph);
            float d2[4][2][4];
            tile_mlp<N_SA2, 9>(dsm, sbase, s * N_SLOT, s * N_SLOT + N_ALOD, N_H,
                               g_wn1f, g_wn2f, b1s, wid, lane, bempty + 8 * s, d2);
#pragma unroll
            for (int m = 0; m < 4; m++) {
                int Rb = 16 * m + (lane >> 2);
#pragma unroll
                for (int h = 0; h < 2; h++) {
                    int row = Rb + 8 * h;
                    int n = t * 64 + row;
                    if (n < N) {
#pragma unroll
                        for (int j = 0; j < 2; j++) {
                            int c = 16 * wid + 8 * j + 2 * (lane & 3);
                            float v0 = d2[m][j][2 * h]     + b2s[c];
                            float v1 = d2[m][j][2 * h + 1] + b2s[c + 1];
                            *(float2*)(nout + (size_t)n * 64 + c) = make_float2(v0, v1);
                            acc[j][0] += v0; acc[j][1] += v1;
                        }
                    }
                }
            }
        }
#pragma unroll
        for (int j = 0; j < 2; j++) {
            atomicAdd(&redbuf[16 * wid + 8 * j + 2 * (lane & 3)], acc[j][0]);
            atomicAdd(&redbuf[16 * wid + 8 * j + 2 * (lane & 3) + 1], acc[j][1]);
        }
        BARC128(2);
        if (tid < 64) atomicAdd(&g_nsum[tid], redbuf[tid]);
    } else {  // producers
        const int pt = tid - 128;
        const int e = pt >> 2, q = pt & 3;
        int i = 0;
        for (int t = blockIdx.x; t < ntiles; t += gridDim.x, i++) {
            int s = i & 1;
            if (i >= 2) mbar_wait(bempty + 8 * s, ((i >> 1) + 1) & 1);
            int n = t * 64 + e;
            bool v = n < N;
            float inv = 1.f;
            if (v) inv = 1.0f / fmaxf(g_cnt[n], 1.0f);
            char* sb = dsm + s * N_SLOT;
            const float4* g4 = (const float4*)gf;
            const float4* xn = (const float4*)(x + (size_t)n * 64);
            const float4* sg = (const float4*)(g_segsum + (size_t)n * 64);
            float4 vv[9];
#pragma unroll
            for (int j = 0; j < 9; j++) {
                int c4 = q + 4 * j;
                float4 w = make_float4(0.f, 0.f, 0.f, 0.f);
                if (v) {
                    if (c4 < 4) w = g4[c4];
                    else if (c4 < 20) w = xn[c4 - 4];
                    else {
                        float4 p = sg[c4 - 20];
                        w = make_float4(p.x * inv, p.y * inv, p.z * inv, p.w * inv);
                    }
                }
                vv[j] = w;
            }
#pragma unroll
            for (int j = 0; j < 9; j++) {
                int c4 = q + 4 * j;
                uint32_t h0, l0, h1, l1;
                split2h(vv[j].x, vv[j].y, h0, l0);
                split2h(vv[j].z, vv[j].w, h1, l1);
                uint32_t off = (uint32_t)(e * N_SA2 + c4 * 8);
                *(uint2*)(sb + off) = make_uint2(h0, h1);
                *(uint2*)(sb + N_ALOD + off) = make_uint2(l0, l1);
            }
            mbar_arrive(bfull + 8 * s);
        }
    }
}

// ---------------- global kernel ----------------
__global__ void global_kernel(const float* __restrict__ g,
                              const float* __restrict__ Wg1, const float* __restrict__ bg1,
                              const float* __restrict__ Wg2, const float* __restrict__ bg2,
                              float* __restrict__ out, int N, int E)
{
    __shared__ float in[144], h[128];
    int t = threadIdx.x;
    if (t < 64)       in[t] = g_nsum[t] / (float)N;
    else if (t < 128) in[t] = g_esum[t - 64] / (float)E;
    else if (t < 144) in[t] = g[t - 128];
    __syncthreads();
    if (t < 128) {
        float s = bg1[t];
        for (int k = 0; k < 144; k++) s += in[k] * Wg1[(size_t)k * 128 + t];
        h[t] = fmaxf(s, 0.f);
    }
    __syncthreads();
    if (t < 16) {
        float s = bg2[t];
        for (int k = 0; k < 128; k++) s += h[k] * Wg2[(size_t)k * 16 + t];
        out[t] = s;
    }
}

// ---------------- launch ----------------
extern "C" void kernel_launch(void* const* d_in, const int* in_sizes, int n_in,
                              void* d_out, int out_size)
{
    const float* x   = (const float*)d_in[0];
    const int*   ei  = (const int*)d_in[1];
    const float* ea  = (const float*)d_in[2];
    const float* g   = (const float*)d_in[3];
    const float* We1 = (const float*)d_in[4];
    const float* be1 = (const float*)d_in[5];
    const float* We2 = (const float*)d_in[6];
    const float* be2 = (const float*)d_in[7];
    const float* Wn1 = (const float*)d_in[8];
    const float* bn1 = (const float*)d_in[9];
    const float* Wn2 = (const float*)d_in[10];
    const float* bn2 = (const float*)d_in[11];
    const float* Wg1 = (const float*)d_in[12];
    const float* bg1 = (const float*)d_in[13];
    const float* Wg2 = (const float*)d_in[14];
    const float* bg2 = (const float*)d_in[15];

    int N = in_sizes[0] / 64;
    int E = in_sizes[1] / 2;
    float* eout = (float*)d_out;
    float* nout = eout + (size_t)E * 64;
    float* gout = nout + (size_t)N * 64;

    cudaFuncSetAttribute(edge_tc, cudaFuncAttributeMaxDynamicSharedMemorySize, E_SMEM);
    cudaFuncSetAttribute(node_tc, cudaFuncAttributeMaxDynamicSharedMemorySize, N_SMEM);

    zero_kernel<<<(N * 16 + 255) / 256, 256>>>(N);
    prep_weights<<<60, 256>>>(We1, We2, Wn1, Wn2);

    int etiles = (E + 63) / 64;
    int ntl    = (N + 63) / 64;
    edge_tc<<<148, 384, E_SMEM>>>(x, ei, ea, g, be1, be2, eout, E, N, etiles);
    node_tc<<<148, 384, N_SMEM>>>(x, g, bn1, bn2, nout, N, ntl);
    global_kernel<<<1, 160>>>(g, Wg1, bg1, Wg2, bg2, gout, N, E);
}

// round 9
// speedup vs baseline: 4.4508x; 1.2141x over previous
#include <cuda_runtime.h>
#include <cuda_fp16.h>
#include <stdint.h>
#include <math.h>

#define NMAX 100000

__device__ __align__(16) float g_segsum[(size_t)NMAX * 64];
__device__ float g_cnt[NMAX];
__device__ float g_esum[64];
__device__ float g_nsum[64];

// W1: fp16 hi-only fragments uint2 = {b0, b1}; W2: hi/lo uint4. [kc][nt8][lane]
__device__ __align__(16) uint2 g_w1f[13 * 16 * 32];
__device__ __align__(16) uint4 g_w2f[8 * 8 * 32];
__device__ __align__(16) uint2 g_wn1f[9 * 16 * 32];
__device__ __align__(16) uint4 g_wn2f[8 * 8 * 32];

// ---------------- helpers ----------------
__device__ __forceinline__ uint32_t smem_u32(const void* p) {
    uint32_t a;
    asm("{ .reg .u64 t; cvta.to.shared.u64 t, %1; cvt.u32.u64 %0, t; }" : "=r"(a) : "l"(p));
    return a;
}
#define LDSM_X4(r, a) asm volatile( \
    "ldmatrix.sync.aligned.m8n8.x4.shared.b16 {%0,%1,%2,%3}, [%4];" \
    : "=r"((r)[0]), "=r"((r)[1]), "=r"((r)[2]), "=r"((r)[3]) : "r"(a))
#define MMA16816(d, a, b0, b1) asm volatile( \
    "mma.sync.aligned.m16n8k16.row.col.f32.f16.f16.f32 " \
    "{%0,%1,%2,%3}, {%4,%5,%6,%7}, {%8,%9}, {%0,%1,%2,%3};" \
    : "+f"((d)[0]), "+f"((d)[1]), "+f"((d)[2]), "+f"((d)[3]) \
    : "r"((a)[0]), "r"((a)[1]), "r"((a)[2]), "r"((a)[3]), "r"(b0), "r"(b1))
#define BARC256(id) asm volatile("bar.sync %0, 256;" :: "r"(id) : "memory")

__device__ __forceinline__ void mbar_init(uint32_t m, uint32_t c) {
    asm volatile("mbarrier.init.shared.b64 [%0], %1;" :: "r"(m), "r"(c) : "memory");
}
__device__ __forceinline__ void mbar_arrive(uint32_t m) {
    asm volatile("mbarrier.arrive.shared.b64 _, [%0];" :: "r"(m) : "memory");
}
__device__ __forceinline__ void mbar_wait(uint32_t m, int ph) {
    asm volatile("{ .reg .pred P;\nLW%=: mbarrier.try_wait.parity.acquire.cta.shared::cta.b64 P, [%0], %1, 0x989680;\n@P bra LD%=;\nbra LW%=;\nLD%=: }"
                 :: "r"(m), "r"(ph) : "memory");
}
__device__ __forceinline__ void split2h(float v0, float v1, uint32_t& h, uint32_t& l) {
    __half2 H = __floats2half2_rn(v0, v1);
    float2 hf = __half22float2(H);
    __half2 L = __floats2half2_rn(v0 - hf.x, v1 - hf.y);
    h = *(uint32_t*)&H;
    l = *(uint32_t*)&L;
}
__device__ __forceinline__ void redv2(float* p, float a, float b) {
    asm volatile("{ .reg .u64 q; cvta.to.global.u64 q, %0;\n"
                 "red.global.add.v2.f32 [q], {%1,%2}; }"
                 :: "l"(p), "f"(a), "f"(b) : "memory");
}

// ---------------- setup ----------------
__global__ void zero_kernel(int N) {
    size_t i = (size_t)blockIdx.x * blockDim.x + threadIdx.x;
    if (i < (size_t)N * 16) ((float4*)g_segsum)[i] = make_float4(0.f, 0.f, 0.f, 0.f);
    if (i < (size_t)N) g_cnt[i] = 0.f;
    if (i < 64) { g_esum[i] = 0.f; g_nsum[i] = 0.f; }
}
__device__ __forceinline__ uint2 mkfrag2(const float* W, int ncols, int kc, int nt8, int lane) {
    int k0 = kc * 16 + 2 * (lane & 3);
    int n  = nt8 * 8 + (lane >> 2);
    __half2 a = __floats2half2_rn(W[(size_t)k0 * ncols + n], W[(size_t)(k0 + 1) * ncols + n]);
    __half2 b = __floats2half2_rn(W[(size_t)(k0 + 8) * ncols + n], W[(size_t)(k0 + 9) * ncols + n]);
    return make_uint2(*(uint32_t*)&a, *(uint32_t*)&b);
}
__device__ __forceinline__ uint4 mkfrag4(const float* W, int ncols, int kc, int nt8, int lane) {
    int k0 = kc * 16 + 2 * (lane & 3);
    int n  = nt8 * 8 + (lane >> 2);
    uint32_t h0, l0, h1, l1;
    split2h(W[(size_t)k0 * ncols + n], W[(size_t)(k0 + 1) * ncols + n], h0, l0);
    split2h(W[(size_t)(k0 + 8) * ncols + n], W[(size_t)(k0 + 9) * ncols + n], h1, l1);
    return make_uint4(h0, h1, l0, l1);
}
__global__ void prep_weights(const float* We1, const float* We2,
                             const float* Wn1, const float* Wn2) {
    int i = blockIdx.x * blockDim.x + threadIdx.x;
    if (i < 13 * 16 * 32) { int kc = i >> 9, r = i & 511; g_w1f[i] = mkfrag2(We1, 128, kc, r >> 5, r & 31); return; }
    i -= 13 * 16 * 32;
    if (i < 8 * 8 * 32)   { int kc = i >> 8, r = i & 255; g_w2f[i] = mkfrag4(We2, 64, kc, r >> 5, r & 31); return; }
    i -= 8 * 8 * 32;
    if (i < 9 * 16 * 32)  { int kc = i >> 9, r = i & 511; g_wn1f[i] = mkfrag2(Wn1, 128, kc, r >> 5, r & 31); return; }
    i -= 9 * 16 * 32;
    if (i < 8 * 8 * 32)   { int kc = i >> 8, r = i & 255; g_wn2f[i] = mkfrag4(Wn2, 64, kc, r >> 5, r & 31); }
}

// ---------------- consumer MLP: 8 warps, 2M x 4N, 64-row tile ----------------
// warp (wm, wn): rows [32wm, 32wm+32), GEMM1 cols [32wn,+32), GEMM2 cols [16wn,+16)
template<int SA2, int KC1>
__device__ __forceinline__ void tile_mlp(char* sm, uint32_t sbase,
    uint32_t offAhi, uint32_t offAlo, uint32_t offH,
    const uint2* __restrict__ W1f, const uint4* __restrict__ W2f,
    const float* b1s, int wm, int wn, int lane, uint32_t emptyAddr,
    float (&d2)[2][2][4])
{
    float d1[2][4][4];
#pragma unroll
    for (int m = 0; m < 2; m++)
#pragma unroll
        for (int j = 0; j < 4; j++)
#pragma unroll
            for (int k = 0; k < 4; k++) d1[m][j][k] = 0.f;

    const uint32_t aoff = (uint32_t)(32 * wm * SA2 + (lane & 15) * SA2 + (lane >> 4) * 16);
    const uint32_t aAh = sbase + offAhi + aoff;
    const uint32_t aAl = sbase + offAlo + aoff;
    const uint2* __restrict__ w1p = W1f + 4 * wn * 32 + lane;

    for (int kc = 0; kc < KC1; kc++) {
        uint32_t ah[2][4], al[2][4];
#pragma unroll
        for (int m = 0; m < 2; m++) {
            LDSM_X4(ah[m], aAh + (uint32_t)(m * 16 * SA2) + kc * 32);
            LDSM_X4(al[m], aAl + (uint32_t)(m * 16 * SA2) + kc * 32);
        }
        uint2 w[4];
#pragma unroll
        for (int j = 0; j < 4; j++) w[j] = __ldg(w1p + kc * 512 + j * 32);
#pragma unroll
        for (int m = 0; m < 2; m++)
#pragma unroll
            for (int j = 0; j < 4; j++) {
                MMA16816(d1[m][j], ah[m], w[j].x, w[j].y);
                MMA16816(d1[m][j], al[m], w[j].x, w[j].y);
            }
    }
    mbar_arrive(emptyAddr);   // A slot free for producer

    // epi1: H = relu(D1 + b1) -> fp16, stride 136 halves (272B)
#pragma unroll
    for (int m = 0; m < 2; m++)
#pragma unroll
        for (int j = 0; j < 4; j++) {
            int c = 32 * wn + 8 * j + 2 * (lane & 3);
            int R = 32 * wm + 16 * m + (lane >> 2);
            __half2 p0 = __floats2half2_rn(fmaxf(d1[m][j][0] + b1s[c], 0.f),
                                           fmaxf(d1[m][j][1] + b1s[c + 1], 0.f));
            *(__half2*)(sm + offH + (R * 136 + c) * 2) = p0;
            __half2 p1 = __floats2half2_rn(fmaxf(d1[m][j][2] + b1s[c], 0.f),
                                           fmaxf(d1[m][j][3] + b1s[c + 1], 0.f));
            *(__half2*)(sm + offH + ((R + 8) * 136 + c) * 2) = p1;
        }
    BARC256(1);   // H visible to all consumer warps

    // GEMM2: 32 rows x 16 cols per warp, K=128, 2 terms (Hh*W2h + Hh*W2l)
#pragma unroll
    for (int m = 0; m < 2; m++)
#pragma unroll
        for (int j = 0; j < 2; j++)
#pragma unroll
            for (int k = 0; k < 4; k++) d2[m][j][k] = 0.f;

    const uint32_t hoff = (uint32_t)(32 * wm * 272 + (lane & 15) * 272 + (lane >> 4) * 16);
    const uint32_t aH = sbase + offH + hoff;
    const uint4* __restrict__ w2p = W2f + 2 * wn * 32 + lane;

#pragma unroll
    for (int kc = 0; kc < 8; kc++) {
        uint32_t hh[2][4];
#pragma unroll
        for (int m = 0; m < 2; m++)
            LDSM_X4(hh[m], aH + (uint32_t)(m * 16 * 272) + kc * 32);
        uint4 w0 = __ldg(w2p + kc * 256);
        uint4 w1 = __ldg(w2p + kc * 256 + 32);
#pragma unroll
        for (int m = 0; m < 2; m++) {
            MMA16816(d2[m][0], hh[m], w0.x, w0.y);
            MMA16816(d2[m][0], hh[m], w0.z, w0.w);
            MMA16816(d2[m][1], hh[m], w1.x, w1.y);
            MMA16816(d2[m][1], hh[m], w1.z, w1.w);
        }
    }
    BARC256(1);   // all H reads done -> next tile's epi1 may overwrite H
}

// ---------------- edge kernel ----------------
extern __shared__ char dsm[];

#define E_SA2  432
#define E_SLOT 55296u
#define E_ALOD 27648u
#define E_H    110592u
#define E_SMEM 128000

__global__ __launch_bounds__(512, 1)
void edge_tc(const float* __restrict__ x, const int* __restrict__ ei,
             const float* __restrict__ ea, const float* __restrict__ gf,
             const float* __restrict__ b1, const float* __restrict__ b2,
             float* __restrict__ eout, int E, int N, int ntiles)
{
    __shared__ float b1s[128], b2s[64], redbuf[64];
    __shared__ __align__(16) unsigned long long s_bar[4];
    const int tid = threadIdx.x, lane = tid & 31;
    const uint32_t sbase = smem_u32(dsm);
    const uint32_t bfull = smem_u32(&s_bar[0]), bempty = smem_u32(&s_bar[2]);

    if (tid < 128) b1s[tid] = b1[tid];
    if (tid < 64)  { b2s[tid] = b2[tid]; redbuf[tid] = 0.f; }
    if (tid == 0) {
        mbar_init(bfull, 256); mbar_init(bfull + 8, 256);
        mbar_init(bempty, 256); mbar_init(bempty + 8, 256);
    }
    __syncthreads();

    if (tid < 256) {  // ---- consumers (8 warps: 2M x 4N) ----
        const int wid = tid >> 5, wm = wid >> 2, wn = wid & 3;
        float acc[2][2] = {{0.f, 0.f}, {0.f, 0.f}};
        int i = 0;
        for (int t = blockIdx.x; t < ntiles; t += gridDim.x, i++) {
            int s = i & 1, ph = (i >> 1) & 1;
            mbar_wait(bfull + 8 * s, ph);
            float d2[2][2][4];
            tile_mlp<E_SA2, 13>(dsm, sbase, s * E_SLOT, s * E_SLOT + E_ALOD, E_H,
                                g_w1f, g_w2f, b1s, wm, wn, lane, bempty + 8 * s, d2);
#pragma unroll
            for (int m = 0; m < 2; m++)
#pragma unroll
                for (int h = 0; h < 2; h++) {
                    int row = 32 * wm + 16 * m + (lane >> 2) + 8 * h;
                    int ge = t * 64 + row;
                    if (ge < E) {
                        int r = ei[ge]; r = min(max(r, 0), N - 1);
#pragma unroll
                        for (int j = 0; j < 2; j++) {
                            int c = 16 * wn + 8 * j + 2 * (lane & 3);
                            float v0 = d2[m][j][2 * h]     + b2s[c];
                            float v1 = d2[m][j][2 * h + 1] + b2s[c + 1];
                            *(float2*)(eout + (size_t)ge * 64 + c) = make_float2(v0, v1);
                            redv2(g_segsum + (size_t)r * 64 + c, v0, v1);
                            acc[j][0] += v0; acc[j][1] += v1;
                        }
                        if (wn == 0 && (lane & 3) == 0) atomicAdd(&g_cnt[r], 1.f);
                    }
                }
        }
#pragma unroll
        for (int j = 0; j < 2; j++) {
            atomicAdd(&redbuf[16 * wn + 8 * j + 2 * (lane & 3)], acc[j][0]);
            atomicAdd(&redbuf[16 * wn + 8 * j + 2 * (lane & 3) + 1], acc[j][1]);
        }
        BARC256(2);
        if (tid < 64) atomicAdd(&g_esum[tid], redbuf[tid]);
    } else {  // ---- producers (8 warps, 4 threads/row) ----
        const int pt = tid - 256;
        const int e = pt >> 2, q = pt & 3;
        int i = 0;
        for (int t = blockIdx.x; t < ntiles; t += gridDim.x, i++) {
            int s = i & 1;
            if (i >= 2) mbar_wait(bempty + 8 * s, ((i >> 1) + 1) & 1);
            int ge = t * 64 + e;
            bool v = ge < E;
            int r = 0, c = 0;
            if (v) {
                r = ei[ge]; c = ei[E + ge];
                r = min(max(r, 0), N - 1); c = min(max(c, 0), N - 1);
            }
            char* sb = dsm + s * E_SLOT;
            const float4* g4 = (const float4*)gf;
            const float4* xr = (const float4*)(x + (size_t)r * 64);
            const float4* xc = (const float4*)(x + (size_t)c * 64);
            const float4* e4 = (const float4*)(ea + (size_t)ge * 64);
            float4 vv[13];
#pragma unroll
            for (int j = 0; j < 13; j++) {
                int c4 = q + 4 * j;
                float4 w = make_float4(0.f, 0.f, 0.f, 0.f);
                if (v) {
                    if (c4 < 4) w = g4[c4];
                    else if (c4 < 20) w = xr[c4 - 4];
                    else if (c4 < 36) w = xc[c4 - 20];
                    else w = e4[c4 - 36];
                }
                vv[j] = w;
            }
#pragma unroll
            for (int j = 0; j < 13; j++) {
                int c4 = q + 4 * j;
                uint32_t h0, l0, h1, l1;
                split2h(vv[j].x, vv[j].y, h0, l0);
                split2h(vv[j].z, vv[j].w, h1, l1);
                uint32_t off = (uint32_t)(e * E_SA2 + c4 * 8);
                *(uint2*)(sb + off) = make_uint2(h0, h1);
                *(uint2*)(sb + E_ALOD + off) = make_uint2(l0, l1);
            }
            mbar_arrive(bfull + 8 * s);
        }
    }
}

// ---------------- node kernel ----------------
#define N_SA2  304
#define N_SLOT 38912u
#define N_ALOD 19456u
#define N_H    77824u
#define N_SMEM 95232

__global__ __launch_bounds__(512, 1)
void node_tc(const float* __restrict__ x, const float* __restrict__ gf,
             const float* __restrict__ b1, const float* __restrict__ b2,
             float* __restrict__ nout, int N, int ntiles)
{
    __shared__ float b1s[128], b2s[64], redbuf[64];
    __shared__ __align__(16) unsigned long long s_bar[4];
    const int tid = threadIdx.x, lane = tid & 31;
    const uint32_t sbase = smem_u32(dsm);
    const uint32_t bfull = smem_u32(&s_bar[0]), bempty = smem_u32(&s_bar[2]);

    if (tid < 128) b1s[tid] = b1[tid];
    if (tid < 64)  { b2s[tid] = b2[tid]; redbuf[tid] = 0.f; }
    if (tid == 0) {
        mbar_init(bfull, 256); mbar_init(bfull + 8, 256);
        mbar_init(bempty, 256); mbar_init(bempty + 8, 256);
    }
    __syncthreads();

    if (tid < 256) {  // consumers
        const int wid = tid >> 5, wm = wid >> 2, wn = wid & 3;
        float acc[2][2] = {{0.f, 0.f}, {0.f, 0.f}};
        int i = 0;
        for (int t = blockIdx.x; t < ntiles; t += gridDim.x, i++) {
            int s = i & 1, ph = (i >> 1) & 1;
            mbar_wait(bfull + 8 * s, ph);
            float d2[2][2][4];
            tile_mlp<N_SA2, 9>(dsm, sbase, s * N_SLOT, s * N_SLOT + N_ALOD, N_H,
                               g_wn1f, g_wn2f, b1s, wm, wn, lane, bempty + 8 * s, d2);
#pragma unroll
            for (int m = 0; m < 2; m++)
#pragma unroll
                for (int h = 0; h < 2; h++) {
                    int row = 32 * wm + 16 * m + (lane >> 2) + 8 * h;
                    int n = t * 64 + row;
                    if (n < N) {
#pragma unroll
                        for (int j = 0; j < 2; j++) {
                            int c = 16 * wn + 8 * j + 2 * (lane & 3);
                            float v0 = d2[m][j][2 * h]     + b2s[c];
                            float v1 = d2[m][j][2 * h + 1] + b2s[c + 1];
                            *(float2*)(nout + (size_t)n * 64 + c) = make_float2(v0, v1);
                            acc[j][0] += v0; acc[j][1] += v1;
                        }
                    }
                }
        }
#pragma unroll
        for (int j = 0; j < 2; j++) {
            atomicAdd(&redbuf[16 * wn + 8 * j + 2 * (lane & 3)], acc[j][0]);
            atomicAdd(&redbuf[16 * wn + 8 * j + 2 * (lane & 3) + 1], acc[j][1]);
        }
        BARC256(2);
        if (tid < 64) atomicAdd(&g_nsum[tid], redbuf[tid]);
    } else {  // producers
        const int pt = tid - 256;
        const int e = pt >> 2, q = pt & 3;
        int i = 0;
        for (int t = blockIdx.x; t < ntiles; t += gridDim.x, i++) {
            int s = i & 1;
            if (i >= 2) mbar_wait(bempty + 8 * s, ((i >> 1) + 1) & 1);
            int n = t * 64 + e;
            bool v = n < N;
            float inv = 1.f;
            if (v) inv = 1.0f / fmaxf(g_cnt[n], 1.0f);
            char* sb = dsm + s * N_SLOT;
            const float4* g4 = (const float4*)gf;
            const float4* xn = (const float4*)(x + (size_t)n * 64);
            const float4* sg = (const float4*)(g_segsum + (size_t)n * 64);
            float4 vv[9];
#pragma unroll
            for (int j = 0; j < 9; j++) {
                int c4 = q + 4 * j;
                float4 w = make_float4(0.f, 0.f, 0.f, 0.f);
                if (v) {
                    if (c4 < 4) w = g4[c4];
                    else if (c4 < 20) w = xn[c4 - 4];
                    else {
                        float4 p = sg[c4 - 20];
                        w = make_float4(p.x * inv, p.y * inv, p.z * inv, p.w * inv);
                    }
                }
                vv[j] = w;
            }
#pragma unroll
            for (int j = 0; j < 9; j++) {
                int c4 = q + 4 * j;
                uint32_t h0, l0, h1, l1;
                split2h(vv[j].x, vv[j].y, h0, l0);
                split2h(vv[j].z, vv[j].w, h1, l1);
                uint32_t off = (uint32_t)(e * N_SA2 + c4 * 8);
                *(uint2*)(sb + off) = make_uint2(h0, h1);
                *(uint2*)(sb + N_ALOD + off) = make_uint2(l0, l1);
            }
            mbar_arrive(bfull + 8 * s);
        }
    }
}

// ---------------- global kernel ----------------
__global__ void global_kernel(const float* __restrict__ g,
                              const float* __restrict__ Wg1, const float* __restrict__ bg1,
                              const float* __restrict__ Wg2, const float* __restrict__ bg2,
                              float* __restrict__ out, int N, int E)
{
    __shared__ float in[144], h[128];
    int t = threadIdx.x;
    if (t < 64)       in[t] = g_nsum[t] / (float)N;
    else if (t < 128) in[t] = g_esum[t - 64] / (float)E;
    else if (t < 144) in[t] = g[t - 128];
    __syncthreads();
    if (t < 128) {
        float s = bg1[t];
        for (int k = 0; k < 144; k++) s += in[k] * Wg1[(size_t)k * 128 + t];
        h[t] = fmaxf(s, 0.f);
    }
    __syncthreads();
    if (t < 16) {
        float s = bg2[t];
        for (int k = 0; k < 128; k++) s += h[k] * Wg2[(size_t)k * 16 + t];
        out[t] = s;
    }
}

// ---------------- launch ----------------
extern "C" void kernel_launch(void* const* d_in, const int* in_sizes, int n_in,
                              void* d_out, int out_size)
{
    const float* x   = (const float*)d_in[0];
    const int*   ei  = (const int*)d_in[1];
    const float* ea  = (const float*)d_in[2];
    const float* g   = (const float*)d_in[3];
    const float* We1 = (const float*)d_in[4];
    const float* be1 = (const float*)d_in[5];
    const float* We2 = (const float*)d_in[6];
    const float* be2 = (const float*)d_in[7];
    const float* Wn1 = (const float*)d_in[8];
    const float* bn1 = (const float*)d_in[9];
    const float* Wn2 = (const float*)d_in[10];
    const float* bn2 = (const float*)d_in[11];
    const float* Wg1 = (const float*)d_in[12];
    const float* bg1 = (const float*)d_in[13];
    const float* Wg2 = (const float*)d_in[14];
    const float* bg2 = (const float*)d_in[15];

    int N = in_sizes[0] / 64;
    int E = in_sizes[1] / 2;
    float* eout = (float*)d_out;
    float* nout = eout + (size_t)E * 64;
    float* gout = nout + (size_t)N * 64;

    cudaFuncSetAttribute(edge_tc, cudaFuncAttributeMaxDynamicSharedMemorySize, E_SMEM);
    cudaFuncSetAttribute(node_tc, cudaFuncAttributeMaxDynamicSharedMemorySize, N_SMEM);

    zero_kernel<<<(N * 16 + 255) / 256, 256>>>(N);
    prep_weights<<<60, 256>>>(We1, We2, Wn1, Wn2);

    int etiles = (E + 63) / 64;
    int ntl    = (N + 63) / 64;
    edge_tc<<<148, 512, E_SMEM>>>(x, ei, ea, g, be1, be2, eout, E, N, etiles);
    node_tc<<<148, 512, N_SMEM>>>(x, g, bn1, bn2, nout, N, ntl);
    global_kernel<<<1, 160>>>(g, Wg1, bg1, Wg2, bg2, gout, N, E);
}

// round 10
// speedup vs baseline: 5.9545x; 1.3379x over previous
#include <cuda_runtime.h>
#include <cuda_fp16.h>
#include <stdint.h>
#include <math.h>

#define NMAX 100000

__device__ __align__(16) float g_segsum[(size_t)NMAX * 64];
__device__ float g_cnt[NMAX];
__device__ float g_esum[64];
__device__ float g_nsum[64];

// W1: fp16 hi-only fragments uint2; W2: hi/lo uint4. [kc][nt8][lane]
__device__ __align__(16) uint2 g_w1f[13 * 16 * 32];
__device__ __align__(16) uint4 g_w2f[8 * 8 * 32];
__device__ __align__(16) uint2 g_wn1f[9 * 16 * 32];
__device__ __align__(16) uint4 g_wn2f[8 * 8 * 32];

// ---------------- helpers ----------------
__device__ __forceinline__ uint32_t smem_u32(const void* p) {
    uint32_t a;
    asm("{ .reg .u64 t; cvta.to.shared.u64 t, %1; cvt.u32.u64 %0, t; }" : "=r"(a) : "l"(p));
    return a;
}
#define LDSM_X4(r, a) asm volatile( \
    "ldmatrix.sync.aligned.m8n8.x4.shared.b16 {%0,%1,%2,%3}, [%4];" \
    : "=r"((r)[0]), "=r"((r)[1]), "=r"((r)[2]), "=r"((r)[3]) : "r"(a))
#define MMA16816(d, a, b0, b1) asm volatile( \
    "mma.sync.aligned.m16n8k16.row.col.f32.f16.f16.f32 " \
    "{%0,%1,%2,%3}, {%4,%5,%6,%7}, {%8,%9}, {%0,%1,%2,%3};" \
    : "+f"((d)[0]), "+f"((d)[1]), "+f"((d)[2]), "+f"((d)[3]) \
    : "r"((a)[0]), "r"((a)[1]), "r"((a)[2]), "r"((a)[3]), "r"(b0), "r"(b1))
#define BARC256(id) asm volatile("bar.sync %0, 256;" :: "r"(id) : "memory")

__device__ __forceinline__ void mbar_init(uint32_t m, uint32_t c) {
    asm volatile("mbarrier.init.shared.b64 [%0], %1;" :: "r"(m), "r"(c) : "memory");
}
__device__ __forceinline__ void mbar_arrive(uint32_t m) {
    asm volatile("mbarrier.arrive.shared.b64 _, [%0];" :: "r"(m) : "memory");
}
__device__ __forceinline__ void mbar_wait(uint32_t m, int ph) {
    asm volatile("{ .reg .pred P;\nLW%=: mbarrier.try_wait.parity.acquire.cta.shared::cta.b64 P, [%0], %1, 0x989680;\n@P bra LD%=;\nbra LW%=;\nLD%=: }"
                 :: "r"(m), "r"(ph) : "memory");
}
__device__ __forceinline__ void split2h(float v0, float v1, uint32_t& h, uint32_t& l) {
    __half2 H = __floats2half2_rn(v0, v1);
    float2 hf = __half22float2(H);
    __half2 L = __floats2half2_rn(v0 - hf.x, v1 - hf.y);
    h = *(uint32_t*)&H;
    l = *(uint32_t*)&L;
}
__device__ __forceinline__ void redv2(float* p, float a, float b) {
    asm volatile("{ .reg .u64 q; cvta.to.global.u64 q, %0;\n"
                 "red.global.add.v2.f32 [q], {%1,%2}; }"
                 :: "l"(p), "f"(a), "f"(b) : "memory");
}

// ---------------- setup ----------------
__global__ void zero_kernel(int N) {
    size_t i = (size_t)blockIdx.x * blockDim.x + threadIdx.x;
    if (i < (size_t)N * 16) ((float4*)g_segsum)[i] = make_float4(0.f, 0.f, 0.f, 0.f);
    if (i < (size_t)N) g_cnt[i] = 0.f;
    if (i < 64) { g_esum[i] = 0.f; g_nsum[i] = 0.f; }
}
__device__ __forceinline__ uint2 mkfrag2(const float* W, int ncols, int kc, int nt8, int lane) {
    int k0 = kc * 16 + 2 * (lane & 3);
    int n  = nt8 * 8 + (lane >> 2);
    __half2 a = __floats2half2_rn(W[(size_t)k0 * ncols + n], W[(size_t)(k0 + 1) * ncols + n]);
    __half2 b = __floats2half2_rn(W[(size_t)(k0 + 8) * ncols + n], W[(size_t)(k0 + 9) * ncols + n]);
    return make_uint2(*(uint32_t*)&a, *(uint32_t*)&b);
}
__device__ __forceinline__ uint4 mkfrag4(const float* W, int ncols, int kc, int nt8, int lane) {
    int k0 = kc * 16 + 2 * (lane & 3);
    int n  = nt8 * 8 + (lane >> 2);
    uint32_t h0, l0, h1, l1;
    split2h(W[(size_t)k0 * ncols + n], W[(size_t)(k0 + 1) * ncols + n], h0, l0);
    split2h(W[(size_t)(k0 + 8) * ncols + n], W[(size_t)(k0 + 9) * ncols + n], h1, l1);
    return make_uint4(h0, h1, l0, l1);
}
__global__ void prep_weights(const float* We1, const float* We2,
                             const float* Wn1, const float* Wn2) {
    int i = blockIdx.x * blockDim.x + threadIdx.x;
    if (i < 13 * 16 * 32) { int kc = i >> 9, r = i & 511; g_w1f[i] = mkfrag2(We1, 128, kc, r >> 5, r & 31); return; }
    i -= 13 * 16 * 32;
    if (i < 8 * 8 * 32)   { int kc = i >> 8, r = i & 255; g_w2f[i] = mkfrag4(We2, 64, kc, r >> 5, r & 31); return; }
    i -= 8 * 8 * 32;
    if (i < 9 * 16 * 32)  { int kc = i >> 9, r = i & 511; g_wn1f[i] = mkfrag2(Wn1, 128, kc, r >> 5, r & 31); return; }
    i -= 9 * 16 * 32;
    if (i < 8 * 8 * 32)   { int kc = i >> 8, r = i & 255; g_wn2f[i] = mkfrag4(Wn2, 64, kc, r >> 5, r & 31); }
}

// ---------------- consumer MLP: 8 warps (2M x 4N), 64-row tile ----------------
// A fp16 single-stream (byte stride SA2). H fp16 (stride 272B). d2 in regs.
template<int SA2, int KC1>
__device__ __forceinline__ void tile_mlp(char* sm, uint32_t sbase,
    uint32_t offA, uint32_t offH,
    const uint2* __restrict__ W1f, const uint4* __restrict__ W2f,
    const float* b1s, int wm, int wn, int lane, uint32_t emptyAddr,
    float (&d2)[2][2][4])
{
    float d1[2][4][4];
#pragma unroll
    for (int m = 0; m < 2; m++)
#pragma unroll
        for (int j = 0; j < 4; j++)
#pragma unroll
            for (int k = 0; k < 4; k++) d1[m][j][k] = 0.f;

    const uint32_t aA = sbase + offA +
        (uint32_t)(32 * wm * SA2 + (lane & 15) * SA2 + (lane >> 4) * 16);
    const uint2* __restrict__ w1p = W1f + 4 * wn * 32 + lane;

    for (int kc = 0; kc < KC1; kc++) {
        uint32_t ah[2][4];
        LDSM_X4(ah[0], aA + kc * 32);
        LDSM_X4(ah[1], aA + (uint32_t)(16 * SA2) + kc * 32);
        uint2 w[4];
#pragma unroll
        for (int j = 0; j < 4; j++) w[j] = __ldg(w1p + kc * 512 + j * 32);
#pragma unroll
        for (int m = 0; m < 2; m++)
#pragma unroll
            for (int j = 0; j < 4; j++)
                MMA16816(d1[m][j], ah[m], w[j].x, w[j].y);
    }
    mbar_arrive(emptyAddr);   // A slot free for producer

    // epi1: H = relu(D1 + b1) -> fp16, stride 136 halves (272B)
#pragma unroll
    for (int m = 0; m < 2; m++)
#pragma unroll
        for (int j = 0; j < 4; j++) {
            int c = 32 * wn + 8 * j + 2 * (lane & 3);
            int R = 32 * wm + 16 * m + (lane >> 2);
            __half2 p0 = __floats2half2_rn(fmaxf(d1[m][j][0] + b1s[c], 0.f),
                                           fmaxf(d1[m][j][1] + b1s[c + 1], 0.f));
            *(__half2*)(sm + offH + (R * 136 + c) * 2) = p0;
            __half2 p1 = __floats2half2_rn(fmaxf(d1[m][j][2] + b1s[c], 0.f),
                                           fmaxf(d1[m][j][3] + b1s[c + 1], 0.f));
            *(__half2*)(sm + offH + ((R + 8) * 136 + c) * 2) = p1;
        }
    BARC256(1);   // H visible to all consumer warps

    // GEMM2: 32 rows x 16 cols per warp, K=128, 2 terms (Hh*W2h + Hh*W2l)
#pragma unroll
    for (int m = 0; m < 2; m++)
#pragma unroll
        for (int j = 0; j < 2; j++)
#pragma unroll
            for (int k = 0; k < 4; k++) d2[m][j][k] = 0.f;

    const uint32_t aH = sbase + offH +
        (uint32_t)(32 * wm * 272 + (lane & 15) * 272 + (lane >> 4) * 16);
    const uint4* __restrict__ w2p = W2f + 2 * wn * 32 + lane;

#pragma unroll
    for (int kc = 0; kc < 8; kc++) {
        uint32_t hh[2][4];
        LDSM_X4(hh[0], aH + kc * 32);
        LDSM_X4(hh[1], aH + (uint32_t)(16 * 272) + kc * 32);
        uint4 w0 = __ldg(w2p + kc * 256);
        uint4 w1 = __ldg(w2p + kc * 256 + 32);
#pragma unroll
        for (int m = 0; m < 2; m++) {
            MMA16816(d2[m][0], hh[m], w0.x, w0.y);
            MMA16816(d2[m][0], hh[m], w0.z, w0.w);
            MMA16816(d2[m][1], hh[m], w1.x, w1.y);
            MMA16816(d2[m][1], hh[m], w1.z, w1.w);
        }
    }
    BARC256(1);   // all H reads done -> next tile's epi1 may overwrite H
}

// ---------------- edge kernel ----------------
extern __shared__ char dsm[];

#define E_SA2  432
#define E_SLOT 27648u
#define E_H    55296u
#define E_SMEM 72704

__global__ __launch_bounds__(512, 1)
void edge_tc(const float* __restrict__ x, const int* __restrict__ ei,
             const float* __restrict__ ea, const float* __restrict__ gf,
             const float* __restrict__ b1, const float* __restrict__ b2,
             float* __restrict__ eout, int E, int N, int ntiles)
{
    __shared__ float b1s[128], b2s[64], redbuf[64];
    __shared__ __align__(16) unsigned long long s_bar[4];
    const int tid = threadIdx.x, lane = tid & 31;
    const uint32_t sbase = smem_u32(dsm);
    const uint32_t bfull = smem_u32(&s_bar[0]), bempty = smem_u32(&s_bar[2]);

    if (tid < 128) b1s[tid] = b1[tid];
    if (tid < 64)  { b2s[tid] = b2[tid]; redbuf[tid] = 0.f; }
    if (tid == 0) {
        mbar_init(bfull, 256); mbar_init(bfull + 8, 256);
        mbar_init(bempty, 256); mbar_init(bempty + 8, 256);
    }
    __syncthreads();

    if (tid < 256) {  // ---- consumers (8 warps: 2M x 4N) ----
        const int wid = tid >> 5, wm = wid >> 2, wn = wid & 3;
        float acc[2][2] = {{0.f, 0.f}, {0.f, 0.f}};
        int i = 0;
        for (int t = blockIdx.x; t < ntiles; t += gridDim.x, i++) {
            int s = i & 1, ph = (i >> 1) & 1;
            mbar_wait(bfull + 8 * s, ph);
            float d2[2][2][4];
            tile_mlp<E_SA2, 13>(dsm, sbase, s * E_SLOT, E_H,
                                g_w1f, g_w2f, b1s, wm, wn, lane, bempty + 8 * s, d2);
#pragma unroll
            for (int m = 0; m < 2; m++)
#pragma unroll
                for (int h = 0; h < 2; h++) {
                    int row = 32 * wm + 16 * m + (lane >> 2) + 8 * h;
                    int ge = t * 64 + row;
                    if (ge < E) {
                        int r = ei[ge]; r = min(max(r, 0), N - 1);
#pragma unroll
                        for (int j = 0; j < 2; j++) {
                            int c = 16 * wn + 8 * j + 2 * (lane & 3);
                            float v0 = d2[m][j][2 * h]     + b2s[c];
                            float v1 = d2[m][j][2 * h + 1] + b2s[c + 1];
                            *(float2*)(eout + (size_t)ge * 64 + c) = make_float2(v0, v1);
                            redv2(g_segsum + (size_t)r * 64 + c, v0, v1);
                            acc[j][0] += v0; acc[j][1] += v1;
                        }
                        if (wn == 0 && (lane & 3) == 0) atomicAdd(&g_cnt[r], 1.f);
                    }
                }
        }
#pragma unroll
        for (int j = 0; j < 2; j++) {
            atomicAdd(&redbuf[16 * wn + 8 * j + 2 * (lane & 3)], acc[j][0]);
            atomicAdd(&redbuf[16 * wn + 8 * j + 2 * (lane & 3) + 1], acc[j][1]);
        }
        BARC256(2);
        if (tid < 64) atomicAdd(&g_esum[tid], redbuf[tid]);
    } else {  // ---- producers (8 warps, 4 threads/row) ----
        const int pt = tid - 256;
        const int e = pt >> 2, q = pt & 3;
        int i = 0;
        for (int t = blockIdx.x; t < ntiles; t += gridDim.x, i++) {
            int s = i & 1;
            if (i >= 2) mbar_wait(bempty + 8 * s, ((i >> 1) + 1) & 1);
            int ge = t * 64 + e;
            bool v = ge < E;
            int r = 0, c = 0;
            if (v) {
                r = ei[ge]; c = ei[E + ge];
                r = min(max(r, 0), N - 1); c = min(max(c, 0), N - 1);
            }
            char* sb = dsm + s * E_SLOT;
            const float4* g4 = (const float4*)gf;
            const float4* xr = (const float4*)(x + (size_t)r * 64);
            const float4* xc = (const float4*)(x + (size_t)c * 64);
            const float4* e4 = (const float4*)(ea + (size_t)ge * 64);
            float4 vv[13];
#pragma unroll
            for (int j = 0; j < 13; j++) {
                int c4 = q + 4 * j;
                float4 w = make_float4(0.f, 0.f, 0.f, 0.f);
                if (v) {
                    if (c4 < 4) w = g4[c4];
                    else if (c4 < 20) w = xr[c4 - 4];
                    else if (c4 < 36) w = xc[c4 - 20];
                    else w = e4[c4 - 36];
                }
                vv[j] = w;
            }
#pragma unroll
            for (int j = 0; j < 13; j++) {
                int c4 = q + 4 * j;
                __half2 h0 = __floats2half2_rn(vv[j].x, vv[j].y);
                __half2 h1 = __floats2half2_rn(vv[j].z, vv[j].w);
                *(uint2*)(sb + (uint32_t)(e * E_SA2 + c4 * 8)) =
                    make_uint2(*(uint32_t*)&h0, *(uint32_t*)&h1);
            }
            mbar_arrive(bfull + 8 * s);
        }
    }
}

// ---------------- node kernel ----------------
#define N_SA2  304
#define N_SLOT 19456u
#define N_H    38912u
#define N_SMEM 56320

__global__ __launch_bounds__(512, 1)
void node_tc(const float* __restrict__ x, const float* __restrict__ gf,
             const float* __restrict__ b1, const float* __restrict__ b2,
             float* __restrict__ nout, int N, int ntiles)
{
    __shared__ float b1s[128], b2s[64], redbuf[64];
    __shared__ __align__(16) unsigned long long s_bar[4];
    const int tid = threadIdx.x, lane = tid & 31;
    const uint32_t sbase = smem_u32(dsm);
    const uint32_t bfull = smem_u32(&s_bar[0]), bempty = smem_u32(&s_bar[2]);

    if (tid < 128) b1s[tid] = b1[tid];
    if (tid < 64)  { b2s[tid] = b2[tid]; redbuf[tid] = 0.f; }
    if (tid == 0) {
        mbar_init(bfull, 256); mbar_init(bfull + 8, 256);
        mbar_init(bempty, 256); mbar_init(bempty + 8, 256);
    }
    __syncthreads();

    if (tid < 256) {  // consumers
        const int wid = tid >> 5, wm = wid >> 2, wn = wid & 3;
        float acc[2][2] = {{0.f, 0.f}, {0.f, 0.f}};
        int i = 0;
        for (int t = blockIdx.x; t < ntiles; t += gridDim.x, i++) {
            int s = i & 1, ph = (i >> 1) & 1;
            mbar_wait(bfull + 8 * s, ph);
            float d2[2][2][4];
            tile_mlp<N_SA2, 9>(dsm, sbase, s * N_SLOT, N_H,
                               g_wn1f, g_wn2f, b1s, wm, wn, lane, bempty + 8 * s, d2);
#pragma unroll
            for (int m = 0; m < 2; m++)
#pragma unroll
                for (int h = 0; h < 2; h++) {
                    int row = 32 * wm + 16 * m + (lane >> 2) + 8 * h;
                    int n = t * 64 + row;
                    if (n < N) {
#pragma unroll
                        for (int j = 0; j < 2; j++) {
                            int c = 16 * wn + 8 * j + 2 * (lane & 3);
                            float v0 = d2[m][j][2 * h]     + b2s[c];
                            float v1 = d2[m][j][2 * h + 1] + b2s[c + 1];
                            *(float2*)(nout + (size_t)n * 64 + c) = make_float2(v0, v1);
                            acc[j][0] += v0; acc[j][1] += v1;
                        }
                    }
                }
        }
#pragma unroll
        for (int j = 0; j < 2; j++) {
            atomicAdd(&redbuf[16 * wn + 8 * j + 2 * (lane & 3)], acc[j][0]);
            atomicAdd(&redbuf[16 * wn + 8 * j + 2 * (lane & 3) + 1], acc[j][1]);
        }
        BARC256(2);
        if (tid < 64) atomicAdd(&g_nsum[tid], redbuf[tid]);
    } else {  // producers
        const int pt = tid - 256;
        const int e = pt >> 2, q = pt & 3;
        int i = 0;
        for (int t = blockIdx.x; t < ntiles; t += gridDim.x, i++) {
            int s = i & 1;
            if (i >= 2) mbar_wait(bempty + 8 * s, ((i >> 1) + 1) & 1);
            int n = t * 64 + e;
            bool v = n < N;
            float inv = 1.f;
            if (v) inv = 1.0f / fmaxf(g_cnt[n], 1.0f);
            char* sb = dsm + s * N_SLOT;
            const float4* g4 = (const float4*)gf;
            const float4* xn = (const float4*)(x + (size_t)n * 64);
            const float4* sg = (const float4*)(g_segsum + (size_t)n * 64);
            float4 vv[9];
#pragma unroll
            for (int j = 0; j < 9; j++) {
                int c4 = q + 4 * j;
                float4 w = make_float4(0.f, 0.f, 0.f, 0.f);
                if (v) {
                    if (c4 < 4) w = g4[c4];
                    else if (c4 < 20) w = xn[c4 - 4];
                    else {
                        float4 p = sg[c4 - 20];
                        w = make_float4(p.x * inv, p.y * inv, p.z * inv, p.w * inv);
                    }
                }
                vv[j] = w;
            }
#pragma unroll
            for (int j = 0; j < 9; j++) {
                int c4 = q + 4 * j;
                __half2 h0 = __floats2half2_rn(vv[j].x, vv[j].y);
                __half2 h1 = __floats2half2_rn(vv[j].z, vv[j].w);
                *(uint2*)(sb + (uint32_t)(e * N_SA2 + c4 * 8)) =
                    make_uint2(*(uint32_t*)&h0, *(uint32_t*)&h1);
            }
            mbar_arrive(bfull + 8 * s);
        }
    }
}

// ---------------- global kernel ----------------
__global__ void global_kernel(const float* __restrict__ g,
                              const float* __restrict__ Wg1, const float* __restrict__ bg1,
                              const float* __restrict__ Wg2, const float* __restrict__ bg2,
                              float* __restrict__ out, int N, int E)
{
    __shared__ float in[144], h[128];
    int t = threadIdx.x;
    if (t < 64)       in[t] = g_nsum[t] / (float)N;
    else if (t < 128) in[t] = g_esum[t - 64] / (float)E;
    else if (t < 144) in[t] = g[t - 128];
    __syncthreads();
    if (t < 128) {
        float s = bg1[t];
        for (int k = 0; k < 144; k++) s += in[k] * Wg1[(size_t)k * 128 + t];
        h[t] = fmaxf(s, 0.f);
    }
    __syncthreads();
    if (t < 16) {
        float s = bg2[t];
        for (int k = 0; k < 128; k++) s += h[k] * Wg2[(size_t)k * 16 + t];
        out[t] = s;
    }
}

// ---------------- launch ----------------
extern "C" void kernel_launch(void* const* d_in, const int* in_sizes, int n_in,
                              void* d_out, int out_size)
{
    const float* x   = (const float*)d_in[0];
    const int*   ei  = (const int*)d_in[1];
    const float* ea  = (const float*)d_in[2];
    const float* g   = (const float*)d_in[3];
    const float* We1 = (const float*)d_in[4];
    const float* be1 = (const float*)d_in[5];
    const float* We2 = (const float*)d_in[6];
    const float* be2 = (const float*)d_in[7];
    const float* Wn1 = (const float*)d_in[8];
    const float* bn1 = (const float*)d_in[9];
    const float* Wn2 = (const float*)d_in[10];
    const float* bn2 = (const float*)d_in[11];
    const float* Wg1 = (const float*)d_in[12];
    const float* bg1 = (const float*)d_in[13];
    const float* Wg2 = (const float*)d_in[14];
    const float* bg2 = (const float*)d_in[15];

    int N = in_sizes[0] / 64;
    int E = in_sizes[1] / 2;
    float* eout = (float*)d_out;
    float* nout = eout + (size_t)E * 64;
    float* gout = nout + (size_t)N * 64;

    cudaFuncSetAttribute(edge_tc, cudaFuncAttributeMaxDynamicSharedMemorySize, E_SMEM);
    cudaFuncSetAttribute(node_tc, cudaFuncAttributeMaxDynamicSharedMemorySize, N_SMEM);

    zero_kernel<<<(N * 16 + 255) / 256, 256>>>(N);
    prep_weights<<<60, 256>>>(We1, We2, Wn1, Wn2);

    int etiles = (E + 63) / 64;
    int ntl    = (N + 63) / 64;
    edge_tc<<<148, 512, E_SMEM>>>(x, ei, ea, g, be1, be2, eout, E, N, etiles);
    node_tc<<<148, 512, N_SMEM>>>(x, g, bn1, bn2, nout, N, ntl);
    global_kernel<<<1, 160>>>(g, Wg1, bg1, Wg2, bg2, gout, N, E);
}